// round 1
// baseline (speedup 1.0000x reference)
#include <cuda_runtime.h>

#define TOKENS 200704          // 16*16*16*49
#define DIM 256
#define NQKV 768
#define NWIN 4096
#define WQ 49
#define NKEY 53                // 4 mem + 49
#define NMEM 4
#define DH 32
#define NHEADS 8

typedef unsigned long long ull;

// ---- scratch (static device globals; no runtime allocation) ----
__device__ float g_qkv[(size_t)TOKENS * NQKV];   // 616 MB
__device__ float g_attn[(size_t)TOKENS * DIM];   // 205 MB
__device__ float g_mu[TOKENS];
__device__ float g_rstd[TOKENS];

// ---- packed fp32x2 helpers (Blackwell f32x2 pipe; 2x FFMA throughput) ----
__device__ __forceinline__ ull pk2(float x, float y) {
    ull r; asm("mov.b64 %0, {%1, %2};" : "=l"(r) : "f"(x), "f"(y)); return r;
}
__device__ __forceinline__ void upk2(ull v, float& x, float& y) {
    asm("mov.b64 {%0, %1}, %2;" : "=f"(x), "=f"(y) : "l"(v));
}
__device__ __forceinline__ ull ffma2(ull a, ull b, ull c) {
    ull d; asm("fma.rn.f32x2 %0, %1, %2, %3;" : "=l"(d) : "l"(a), "l"(b), "l"(c)); return d;
}

// ============================================================
// Kernel 1: LayerNorm statistics (one warp per token)
// ============================================================
__global__ void __launch_bounds__(256) ln_stats_kernel(const float* __restrict__ x) {
    int tok  = blockIdx.x * 8 + (threadIdx.x >> 5);
    int lane = threadIdx.x & 31;
    const float4* row = (const float4*)(x + (size_t)tok * DIM);
    float s = 0.f, ss = 0.f;
#pragma unroll
    for (int i = 0; i < 2; i++) {
        float4 v = row[lane + 32 * i];
        s  += (v.x + v.y) + (v.z + v.w);
        ss += v.x * v.x + v.y * v.y + v.z * v.z + v.w * v.w;
    }
#pragma unroll
    for (int o = 16; o; o >>= 1) {
        s  += __shfl_xor_sync(0xffffffffu, s, o);
        ss += __shfl_xor_sync(0xffffffffu, ss, o);
    }
    if (lane == 0) {
        float mu  = s * (1.f / DIM);
        float var = fmaxf(ss * (1.f / DIM) - mu * mu, 0.f);
        g_mu[tok]   = mu;
        g_rstd[tok] = rsqrtf(var + 1e-5f);
    }
}

// ============================================================
// Kernel 2/4: tiled GEMM, M=TOKENS, K=256 fixed, N runtime.
// C[m][n] = sum_k Ahat[m][k] * B[k][n];   Ahat = LN(x) if LN.
// 64x64 tile, BK=32, 256 threads, 4x4 per thread, fp32x2 FFMA.
// A stored in smem as duplicated pairs {a,a} so the mainloop is pure LDS.64 + FFMA2.
// ============================================================
template<bool LN>
__global__ void __launch_bounds__(256) gemm_k256(
    const float* __restrict__ A, const float* __restrict__ B,
    float* __restrict__ C, const float* __restrict__ gamma, int N)
{
    __shared__ float2 As2[32][65];   // [k][m], {a,a} pairs, pad 65 (conflict-light)
    __shared__ float  Bs[32][68];    // [k][n], pad 68 keeps 16B alignment

    const int m0 = blockIdx.y * 64;
    const int n0 = blockIdx.x * 64;
    const int tid = threadIdx.x;
    const int tx = tid & 15;
    const int ty = tid >> 4;

    ull acc[4][2];
#pragma unroll
    for (int i = 0; i < 4; i++) { acc[i][0] = 0ull; acc[i][1] = 0ull; }

    for (int kk = 0; kk < 8; kk++) {
        const int k0 = kk * 32;
        // ---- load A tile (64 rows x 32 k) ----
#pragma unroll
        for (int u = 0; u < 2; u++) {
            int f = tid + u * 256;
            int r = f >> 3, c4 = f & 7;
            float4 v = *((const float4*)(A + (size_t)(m0 + r) * DIM + k0) + c4);
            if (LN) {
                float mu = g_mu[m0 + r], rs = g_rstd[m0 + r];
                const float4 g = *((const float4*)(gamma + k0) + c4);
                v.x = (v.x - mu) * rs * g.x;
                v.y = (v.y - mu) * rs * g.y;
                v.z = (v.z - mu) * rs * g.z;
                v.w = (v.w - mu) * rs * g.w;
            }
            As2[c4 * 4 + 0][r] = make_float2(v.x, v.x);
            As2[c4 * 4 + 1][r] = make_float2(v.y, v.y);
            As2[c4 * 4 + 2][r] = make_float2(v.z, v.z);
            As2[c4 * 4 + 3][r] = make_float2(v.w, v.w);
        }
        // ---- load B tile (32 k x 64 n) ----
#pragma unroll
        for (int u = 0; u < 2; u++) {
            int f = tid + u * 256;
            int r = f >> 4, c4 = f & 15;
            float4 v = *((const float4*)(B + (size_t)(k0 + r) * N + n0) + c4);
            *(float4*)&Bs[r][c4 * 4] = v;
        }
        __syncthreads();
#pragma unroll
        for (int k = 0; k < 32; k++) {
            ull b0 = *(const ull*)&Bs[k][tx * 4];
            ull b1 = *(const ull*)&Bs[k][tx * 4 + 2];
#pragma unroll
            for (int i = 0; i < 4; i++) {
                ull a = *(const ull*)&As2[k][ty * 4 + i];
                acc[i][0] = ffma2(a, b0, acc[i][0]);
                acc[i][1] = ffma2(a, b1, acc[i][1]);
            }
        }
        __syncthreads();
    }
#pragma unroll
    for (int i = 0; i < 4; i++) {
        float4 o;
        upk2(acc[i][0], o.x, o.y);
        upk2(acc[i][1], o.z, o.w);
        *((float4*)(C + (size_t)(m0 + ty * 4 + i) * N + n0 + tx * 4)) = o;
    }
}

// ============================================================
// Kernel 3: per-(window, head) attention.
// One CTA = 64 threads; one query row per thread (49 active).
// ============================================================
__global__ void __launch_bounds__(64) attn_kernel(
    const float* __restrict__ mem_kv, const float* __restrict__ bias_table)
{
    __shared__ float qs[WQ][36];     // pad 36: 16B-aligned rows
    __shared__ float ks[NKEY][DH];
    __shared__ float vs[NKEY][DH];
    __shared__ float bias_s[169];

    const int b = blockIdx.x >> 3;
    const int h = blockIdx.x & 7;
    const int tid = threadIdx.x;
    const size_t tok0 = (size_t)b * WQ;

    // memory k/v rows (0..3)
    if (tid < 32) {
        int m = tid >> 3, c4 = tid & 7;
        float4 kv = *((const float4*)(mem_kv + (size_t)(h * NMEM + m) * DH) + c4);
        *(float4*)&ks[m][c4 * 4] = kv;
        float4 vv = *((const float4*)(mem_kv + (size_t)(NHEADS * NMEM * DH)
                                      + (size_t)(h * NMEM + m) * DH) + c4);
        *(float4*)&vs[m][c4 * 4] = vv;
    }
    // window q/k/v rows
    for (int f = tid; f < WQ * 8; f += 64) {
        int i = f >> 3, c4 = f & 7;
        const float* base = g_qkv + (tok0 + i) * NQKV + h * DH;
        *(float4*)&qs[i][c4 * 4]        = *((const float4*)base + c4);
        *(float4*)&ks[NMEM + i][c4 * 4] = *((const float4*)(base + 256) + c4);
        *(float4*)&vs[NMEM + i][c4 * 4] = *((const float4*)(base + 512) + c4);
    }
    // per-head bias column
    for (int f = tid; f < 169; f += 64)
        bias_s[f] = bias_table[f * NHEADS + h];
    __syncthreads();

    const bool active = tid < WQ;
    float outv[32];
    if (active) {
        const int i = tid;
        ull q2[16];
#pragma unroll
        for (int c4 = 0; c4 < 8; c4++) {
            ulonglong2 t = ((const ulonglong2*)&qs[i][0])[c4];
            q2[c4 * 2] = t.x; q2[c4 * 2 + 1] = t.y;
        }
        float sim[NKEY];
        const float scale = 0.17677669529663687f;   // 1/sqrt(32)
#pragma unroll
        for (int j = 0; j < NKEY; j++) {
            ull s2 = 0ull;
#pragma unroll
            for (int c4 = 0; c4 < 8; c4++) {
                ulonglong2 t = ((const ulonglong2*)&ks[j][0])[c4];
                s2 = ffma2(q2[c4 * 2], t.x, s2);
                s2 = ffma2(q2[c4 * 2 + 1], t.y, s2);
            }
            float lo, hi; upk2(s2, lo, hi);
            sim[j] = (lo + hi) * scale;
        }
        // relative position bias (keys 4..52)
        const int yi = i / 7, xi = i % 7;
#pragma unroll
        for (int j = 0; j < WQ; j++) {
            int yj = j / 7, xj = j % 7;
            int idx = (yi - yj + 6) * 13 + (xi - xj + 6);
            sim[NMEM + j] += bias_s[idx];
        }
        // softmax over 53 keys
        float mx = sim[0];
#pragma unroll
        for (int j = 1; j < NKEY; j++) mx = fmaxf(mx, sim[j]);
        float l = 0.f;
#pragma unroll
        for (int j = 0; j < NKEY; j++) { float p = __expf(sim[j] - mx); sim[j] = p; l += p; }
        float inv = 1.f / l;
        // AV
        ull o2[16];
#pragma unroll
        for (int c = 0; c < 16; c++) o2[c] = 0ull;
#pragma unroll
        for (int j = 0; j < NKEY; j++) {
            ull p2 = pk2(sim[j], sim[j]);
#pragma unroll
            for (int c4 = 0; c4 < 8; c4++) {
                ulonglong2 t = ((const ulonglong2*)&vs[j][0])[c4];
                o2[c4 * 2]     = ffma2(p2, t.x, o2[c4 * 2]);
                o2[c4 * 2 + 1] = ffma2(p2, t.y, o2[c4 * 2 + 1]);
            }
        }
#pragma unroll
        for (int c = 0; c < 16; c++) {
            float lo, hi; upk2(o2[c], lo, hi);
            outv[2 * c] = lo * inv; outv[2 * c + 1] = hi * inv;
        }
        // stage into own qs row (only this thread ever read it)
#pragma unroll
        for (int c4 = 0; c4 < 8; c4++)
            *(float4*)&qs[tid][c4 * 4] = make_float4(outv[c4 * 4 + 0], outv[c4 * 4 + 1],
                                                     outv[c4 * 4 + 2], outv[c4 * 4 + 3]);
    }
    __syncthreads();
    // coalesced store to g_attn[(tok0+i)*256 + h*32 + ...]
    for (int f = tid; f < WQ * 8; f += 64) {
        int i = f >> 3, c4 = f & 7;
        *((float4*)(g_attn + (tok0 + i) * DIM + h * DH) + c4) = *(const float4*)&qs[i][c4 * 4];
    }
}

// ============================================================
extern "C" void kernel_launch(void* const* d_in, const int* in_sizes, int n_in,
                              void* d_out, int out_size) {
    const float* x          = (const float*)d_in[0];
    const float* gamma      = (const float*)d_in[1];
    const float* w_qkv      = (const float*)d_in[2];
    const float* mem_kv     = (const float*)d_in[3];
    const float* bias_table = (const float*)d_in[4];
    const float* w_out      = (const float*)d_in[5];
    float* out = (float*)d_out;

    float* qkv_p;  cudaGetSymbolAddress((void**)&qkv_p,  g_qkv);
    float* attn_p; cudaGetSymbolAddress((void**)&attn_p, g_attn);

    ln_stats_kernel<<<TOKENS / 8, 256>>>(x);
    // n-tile fastest -> A block rows reused out of L2; weights stay L2-resident
    gemm_k256<true ><<<dim3(NQKV / 64, TOKENS / 64), 256>>>(x, w_qkv, qkv_p, gamma, NQKV);
    attn_kernel<<<NWIN * NHEADS, 64>>>(mem_kv, bias_table);
    gemm_k256<false><<<dim3(DIM / 64, TOKENS / 64), 256>>>(attn_p, w_out, out, nullptr, DIM);
}

// round 2
// speedup vs baseline: 1.5237x; 1.5237x over previous
#include <cuda_runtime.h>

#define TOKENS 200704          // 16*16*16*49
#define DIM 256
#define NQKV 768
#define NWIN 4096
#define WQ 49
#define NKEY 53                // 4 mem + 49
#define NMEM 4
#define DH 32
#define NHEADS 8

typedef unsigned long long ull;

// ---- scratch (static device globals; no runtime allocation) ----
__device__ float g_qkv[(size_t)TOKENS * NQKV];   // 616 MB
__device__ float g_attn[(size_t)TOKENS * DIM];   // 205 MB
__device__ float g_mu[TOKENS];
__device__ float g_rstd[TOKENS];

// ---- packed fp32x2 helpers ----
__device__ __forceinline__ ull pk2(float x, float y) {
    ull r; asm("mov.b64 %0, {%1, %2};" : "=l"(r) : "f"(x), "f"(y)); return r;
}
__device__ __forceinline__ void upk2(ull v, float& x, float& y) {
    asm("mov.b64 {%0, %1}, %2;" : "=f"(x), "=f"(y) : "l"(v));
}
__device__ __forceinline__ ull ffma2(ull a, ull b, ull c) {
    ull d; asm("fma.rn.f32x2 %0, %1, %2, %3;" : "=l"(d) : "l"(a), "l"(b), "l"(c)); return d;
}

// ============================================================
// Kernel 1: LayerNorm statistics (one warp per token)
// ============================================================
__global__ void __launch_bounds__(256) ln_stats_kernel(const float* __restrict__ x) {
    int tok  = blockIdx.x * 8 + (threadIdx.x >> 5);
    int lane = threadIdx.x & 31;
    const float4* row = (const float4*)(x + (size_t)tok * DIM);
    float s = 0.f, ss = 0.f;
#pragma unroll
    for (int i = 0; i < 2; i++) {
        float4 v = row[lane + 32 * i];
        s  += (v.x + v.y) + (v.z + v.w);
        ss += v.x * v.x + v.y * v.y + v.z * v.z + v.w * v.w;
    }
#pragma unroll
    for (int o = 16; o; o >>= 1) {
        s  += __shfl_xor_sync(0xffffffffu, s, o);
        ss += __shfl_xor_sync(0xffffffffu, ss, o);
    }
    if (lane == 0) {
        float mu  = s * (1.f / DIM);
        float var = fmaxf(ss * (1.f / DIM) - mu * mu, 0.f);
        g_mu[tok]   = mu;
        g_rstd[tok] = rsqrtf(var + 1e-5f);
    }
}

// ============================================================
// Kernel 2/4: 128x128x16 tiled GEMM, K=256 fixed, fp32x2 FFMA.
// 256 threads, 8x8 per thread, acc paired along n (natural B pairs),
// A splat in-register (no smem duplication). Double-buffered smem.
// ============================================================
template<bool LN>
__global__ void __launch_bounds__(256, 2) gemm_k256(
    const float* __restrict__ A, const float* __restrict__ B,
    float* __restrict__ C, const float* __restrict__ gamma, int N)
{
    // As[buf][k][m], row pad 132 (16B-mult). Reads are ty-broadcast.
    __shared__ float As[2][16][132];
    // Bs[buf][k][chunk*12 + within]: 16 chunks of 8 floats padded to 12
    // (48B stride => distinct bank-quads across the 16 LDS.128 lanes)
    __shared__ float Bs[2][16][192];

    const int m0 = blockIdx.y * 128;
    const int n0 = blockIdx.x * 128;
    const int tid = threadIdx.x;
    const int tx = tid & 15;
    const int ty = tid >> 4;

    // staging indices
    const int am = tid >> 2;            // A row within tile (job0); job1 = +64
    const int ak = (tid & 3) * 4;       // A k quad start
    const int bk = tid >> 5;            // B k row (job0); job1 = +8
    const int bc = tid & 31;            // B float4 column index

    float mu0 = 0.f, rs0 = 1.f, mu1 = 0.f, rs1 = 1.f;
    if (LN) {
        mu0 = g_mu[m0 + am];      rs0 = g_rstd[m0 + am];
        mu1 = g_mu[m0 + am + 64]; rs1 = g_rstd[m0 + am + 64];
    }

    ull acc[8][4];
#pragma unroll
    for (int i = 0; i < 8; i++)
#pragma unroll
        for (int j = 0; j < 4; j++) acc[i][j] = 0ull;

    float4 pa[2], pb[2];

    // ---- load tile 0 ----
    {
        const int k0 = 0;
        pa[0] = *(const float4*)(A + (size_t)(m0 + am) * DIM + k0 + ak);
        pa[1] = *(const float4*)(A + (size_t)(m0 + am + 64) * DIM + k0 + ak);
        pb[0] = *(const float4*)(B + (size_t)(k0 + bk) * N + n0 + bc * 4);
        pb[1] = *(const float4*)(B + (size_t)(k0 + bk + 8) * N + n0 + bc * 4);
    }

    int buf = 0;
    // store tile 0
    {
        float4 g4;
        if (LN) g4 = *(const float4*)(gamma + ak);
#pragma unroll
        for (int j = 0; j < 2; j++) {
            float4 v = pa[j];
            if (LN) {
                float mu = j ? mu1 : mu0, rs = j ? rs1 : rs0;
                v.x = (v.x - mu) * rs * g4.x;
                v.y = (v.y - mu) * rs * g4.y;
                v.z = (v.z - mu) * rs * g4.z;
                v.w = (v.w - mu) * rs * g4.w;
            }
            int m = am + j * 64;
            As[0][ak + 0][m] = v.x;
            As[0][ak + 1][m] = v.y;
            As[0][ak + 2][m] = v.z;
            As[0][ak + 3][m] = v.w;
        }
#pragma unroll
        for (int j = 0; j < 2; j++) {
            int k = bk + j * 8;
            *(float4*)&Bs[0][k][(bc >> 1) * 12 + (bc & 1) * 4] = pb[j];
        }
    }
    __syncthreads();

#pragma unroll 1
    for (int kk = 0; kk < 16; kk++) {
        const bool more = (kk < 15);
        if (more) {
            const int k0 = (kk + 1) * 16;
            pa[0] = *(const float4*)(A + (size_t)(m0 + am) * DIM + k0 + ak);
            pa[1] = *(const float4*)(A + (size_t)(m0 + am + 64) * DIM + k0 + ak);
            pb[0] = *(const float4*)(B + (size_t)(k0 + bk) * N + n0 + bc * 4);
            pb[1] = *(const float4*)(B + (size_t)(k0 + bk + 8) * N + n0 + bc * 4);
        }
        // ---- compute on buf ----
#pragma unroll
        for (int k = 0; k < 16; k++) {
            const float4 av0 = *(const float4*)&As[buf][k][ty * 8];
            const float4 av1 = *(const float4*)&As[buf][k][ty * 8 + 4];
            const ulonglong2 bA = *(const ulonglong2*)&Bs[buf][k][tx * 12];
            const ulonglong2 bB = *(const ulonglong2*)&Bs[buf][k][tx * 12 + 4];
            ull a2[8];
            a2[0] = pk2(av0.x, av0.x); a2[1] = pk2(av0.y, av0.y);
            a2[2] = pk2(av0.z, av0.z); a2[3] = pk2(av0.w, av0.w);
            a2[4] = pk2(av1.x, av1.x); a2[5] = pk2(av1.y, av1.y);
            a2[6] = pk2(av1.z, av1.z); a2[7] = pk2(av1.w, av1.w);
#pragma unroll
            for (int mi = 0; mi < 8; mi++) {
                acc[mi][0] = ffma2(a2[mi], bA.x, acc[mi][0]);
                acc[mi][1] = ffma2(a2[mi], bA.y, acc[mi][1]);
                acc[mi][2] = ffma2(a2[mi], bB.x, acc[mi][2]);
                acc[mi][3] = ffma2(a2[mi], bB.y, acc[mi][3]);
            }
        }
        if (more) {
            const int k0 = (kk + 1) * 16;
            float4 g4;
            if (LN) g4 = *(const float4*)(gamma + k0 + ak);
            const int nb = buf ^ 1;
#pragma unroll
            for (int j = 0; j < 2; j++) {
                float4 v = pa[j];
                if (LN) {
                    float mu = j ? mu1 : mu0, rs = j ? rs1 : rs0;
                    v.x = (v.x - mu) * rs * g4.x;
                    v.y = (v.y - mu) * rs * g4.y;
                    v.z = (v.z - mu) * rs * g4.z;
                    v.w = (v.w - mu) * rs * g4.w;
                }
                int m = am + j * 64;
                As[nb][ak + 0][m] = v.x;
                As[nb][ak + 1][m] = v.y;
                As[nb][ak + 2][m] = v.z;
                As[nb][ak + 3][m] = v.w;
            }
#pragma unroll
            for (int j = 0; j < 2; j++) {
                int k = bk + j * 8;
                *(float4*)&Bs[nb][k][(bc >> 1) * 12 + (bc & 1) * 4] = pb[j];
            }
            __syncthreads();
            buf ^= 1;
        }
    }

    // ---- epilogue: acc pairs along n -> direct float4 stores ----
#pragma unroll
    for (int mi = 0; mi < 8; mi++) {
        float4 o0, o1;
        upk2(acc[mi][0], o0.x, o0.y);
        upk2(acc[mi][1], o0.z, o0.w);
        upk2(acc[mi][2], o1.x, o1.y);
        upk2(acc[mi][3], o1.z, o1.w);
        float* cp = C + (size_t)(m0 + ty * 8 + mi) * N + n0 + tx * 8;
        *(float4*)cp = o0;
        *(float4*)(cp + 4) = o1;
    }
}

// ============================================================
// Kernel 3: per-(window, head) attention. 64 threads, 1 query row/thread.
// ============================================================
__global__ void __launch_bounds__(64) attn_kernel(
    const float* __restrict__ mem_kv, const float* __restrict__ bias_table)
{
    __shared__ float qs[WQ][36];
    __shared__ float ks[NKEY][DH];
    __shared__ float vs[NKEY][DH];
    __shared__ float bias_s[169];

    const int b = blockIdx.x >> 3;
    const int h = blockIdx.x & 7;
    const int tid = threadIdx.x;
    const size_t tok0 = (size_t)b * WQ;

    if (tid < 32) {
        int m = tid >> 3, c4 = tid & 7;
        float4 kv = *((const float4*)(mem_kv + (size_t)(h * NMEM + m) * DH) + c4);
        *(float4*)&ks[m][c4 * 4] = kv;
        float4 vv = *((const float4*)(mem_kv + (size_t)(NHEADS * NMEM * DH)
                                      + (size_t)(h * NMEM + m) * DH) + c4);
        *(float4*)&vs[m][c4 * 4] = vv;
    }
    for (int f = tid; f < WQ * 8; f += 64) {
        int i = f >> 3, c4 = f & 7;
        const float* base = g_qkv + (tok0 + i) * NQKV + h * DH;
        *(float4*)&qs[i][c4 * 4]        = *((const float4*)base + c4);
        *(float4*)&ks[NMEM + i][c4 * 4] = *((const float4*)(base + 256) + c4);
        *(float4*)&vs[NMEM + i][c4 * 4] = *((const float4*)(base + 512) + c4);
    }
    for (int f = tid; f < 169; f += 64)
        bias_s[f] = bias_table[f * NHEADS + h];
    __syncthreads();

    const bool active = tid < WQ;
    if (active) {
        const int i = tid;
        ull q2[16];
#pragma unroll
        for (int c4 = 0; c4 < 8; c4++) {
            ulonglong2 t = ((const ulonglong2*)&qs[i][0])[c4];
            q2[c4 * 2] = t.x; q2[c4 * 2 + 1] = t.y;
        }
        float sim[NKEY];
        const float scale = 0.17677669529663687f;
#pragma unroll
        for (int j = 0; j < NKEY; j++) {
            ull s2 = 0ull;
#pragma unroll
            for (int c4 = 0; c4 < 8; c4++) {
                ulonglong2 t = ((const ulonglong2*)&ks[j][0])[c4];
                s2 = ffma2(q2[c4 * 2], t.x, s2);
                s2 = ffma2(q2[c4 * 2 + 1], t.y, s2);
            }
            float lo, hi; upk2(s2, lo, hi);
            sim[j] = (lo + hi) * scale;
        }
        const int yi = i / 7, xi = i % 7;
#pragma unroll
        for (int j = 0; j < WQ; j++) {
            int yj = j / 7, xj = j % 7;
            int idx = (yi - yj + 6) * 13 + (xi - xj + 6);
            sim[NMEM + j] += bias_s[idx];
        }
        float mx = sim[0];
#pragma unroll
        for (int j = 1; j < NKEY; j++) mx = fmaxf(mx, sim[j]);
        float l = 0.f;
#pragma unroll
        for (int j = 0; j < NKEY; j++) { float p = __expf(sim[j] - mx); sim[j] = p; l += p; }
        float inv = 1.f / l;
        ull o2[16];
#pragma unroll
        for (int c = 0; c < 16; c++) o2[c] = 0ull;
#pragma unroll
        for (int j = 0; j < NKEY; j++) {
            ull p2 = pk2(sim[j], sim[j]);
#pragma unroll
            for (int c4 = 0; c4 < 8; c4++) {
                ulonglong2 t = ((const ulonglong2*)&vs[j][0])[c4];
                o2[c4 * 2]     = ffma2(p2, t.x, o2[c4 * 2]);
                o2[c4 * 2 + 1] = ffma2(p2, t.y, o2[c4 * 2 + 1]);
            }
        }
#pragma unroll
        for (int c4 = 0; c4 < 8; c4++) {
            float a, bx, c, d;
            upk2(o2[c4 * 2], a, bx);
            upk2(o2[c4 * 2 + 1], c, d);
            *(float4*)&qs[tid][c4 * 4] = make_float4(a * inv, bx * inv, c * inv, d * inv);
        }
    }
    __syncthreads();
    for (int f = tid; f < WQ * 8; f += 64) {
        int i = f >> 3, c4 = f & 7;
        *((float4*)(g_attn + (tok0 + i) * DIM + h * DH) + c4) = *(const float4*)&qs[i][c4 * 4];
    }
}

// ============================================================
extern "C" void kernel_launch(void* const* d_in, const int* in_sizes, int n_in,
                              void* d_out, int out_size) {
    const float* x          = (const float*)d_in[0];
    const float* gamma      = (const float*)d_in[1];
    const float* w_qkv      = (const float*)d_in[2];
    const float* mem_kv     = (const float*)d_in[3];
    const float* bias_table = (const float*)d_in[4];
    const float* w_out      = (const float*)d_in[5];
    float* out = (float*)d_out;

    float* qkv_p;  cudaGetSymbolAddress((void**)&qkv_p,  g_qkv);
    float* attn_p; cudaGetSymbolAddress((void**)&attn_p, g_attn);

    ln_stats_kernel<<<TOKENS / 8, 256>>>(x);
    gemm_k256<true ><<<dim3(NQKV / 128, TOKENS / 128), 256>>>(x, w_qkv, qkv_p, gamma, NQKV);
    attn_kernel<<<NWIN * NHEADS, 64>>>(mem_kv, bias_table);
    gemm_k256<false><<<dim3(DIM / 128, TOKENS / 128), 256>>>(attn_p, w_out, out, nullptr, DIM);
}

// round 4
// speedup vs baseline: 2.4579x; 1.6131x over previous
#include <cuda_runtime.h>
#include <cuda_bf16.h>
#include <cstdint>

#define TOKENS 200704          // 16*16*16*49
#define DIM 256
#define NQKV 768
#define NWIN 4096
#define WQ 49
#define NKEY 53
#define NMEM 4
#define DH 32
#define NHEADS 8

typedef unsigned long long ull;

// ---- scratch (static device globals; no runtime allocation) ----
__device__ float g_qkv[(size_t)TOKENS * NQKV];        // 616 MB
__device__ float g_attn[(size_t)TOKENS * DIM];        // 205 MB
__device__ float g_mu[TOKENS];
__device__ float g_rstd[TOKENS];
// fragment-major A (shared by both GEMMs): frag(m16,k16) -> 32 lanes x uint4
__device__ uint4 g_fah[(size_t)(TOKENS / 16) * 16 * 32];   // 102.8 MB
__device__ uint4 g_fal[(size_t)(TOKENS / 16) * 16 * 32];
// fragment-major B: frag(n8,k16) -> 32 lanes x uint2
__device__ uint2 g_fbh1[(NQKV / 8) * 16 * 32];
__device__ uint2 g_fbl1[(NQKV / 8) * 16 * 32];
__device__ uint2 g_fbh2[(DIM / 8) * 16 * 32];
__device__ uint2 g_fbl2[(DIM / 8) * 16 * 32];

// ---- helpers ----
__device__ __forceinline__ uint32_t bpack(float x, float y) {
    __nv_bfloat162 t = __floats2bfloat162_rn(x, y);   // low half = x
    return *(uint32_t*)&t;
}
__device__ __forceinline__ float bhi(float x) {
    return __bfloat162float(__float2bfloat16(x));
}
__device__ __forceinline__ void mma_bf16(float* d, const uint4& a, const uint2& b) {
    asm volatile("mma.sync.aligned.m16n8k16.row.col.f32.bf16.bf16.f32 "
        "{%0,%1,%2,%3}, {%4,%5,%6,%7}, {%8,%9}, {%0,%1,%2,%3};"
        : "+f"(d[0]), "+f"(d[1]), "+f"(d[2]), "+f"(d[3])
        : "r"(a.x), "r"(a.y), "r"(a.z), "r"(a.w), "r"(b.x), "r"(b.y));
}
// packed fp32x2 (attention)
__device__ __forceinline__ ull pk2(float x, float y) {
    ull r; asm("mov.b64 %0, {%1, %2};" : "=l"(r) : "f"(x), "f"(y)); return r;
}
__device__ __forceinline__ void upk2(ull v, float& x, float& y) {
    asm("mov.b64 {%0, %1}, %2;" : "=f"(x), "=f"(y) : "l"(v));
}
__device__ __forceinline__ ull ffma2(ull a, ull b, ull c) {
    ull d; asm("fma.rn.f32x2 %0, %1, %2, %3;" : "=l"(d) : "l"(a), "l"(b), "l"(c)); return d;
}

// ============================================================
// LayerNorm statistics (one warp per token)
// ============================================================
__global__ void __launch_bounds__(256) ln_stats_kernel(const float* __restrict__ x) {
    int tok  = blockIdx.x * 8 + (threadIdx.x >> 5);
    int lane = threadIdx.x & 31;
    const float4* row = (const float4*)(x + (size_t)tok * DIM);
    float s = 0.f, ss = 0.f;
#pragma unroll
    for (int i = 0; i < 2; i++) {
        float4 v = row[lane + 32 * i];
        s  += (v.x + v.y) + (v.z + v.w);
        ss += v.x * v.x + v.y * v.y + v.z * v.z + v.w * v.w;
    }
#pragma unroll
    for (int o = 16; o; o >>= 1) {
        s  += __shfl_xor_sync(0xffffffffu, s, o);
        ss += __shfl_xor_sync(0xffffffffu, ss, o);
    }
    if (lane == 0) {
        float mu  = s * (1.f / DIM);
        float var = fmaxf(ss * (1.f / DIM) - mu * mu, 0.f);
        g_mu[tok]   = mu;
        g_rstd[tok] = rsqrtf(var + 1e-5f);
    }
}

// ============================================================
// Pack A into mma fragment layout, hi/lo bf16 split.
// One warp per frag(m16,k16). Optional fused LayerNorm.
// ============================================================
template<bool LN>
__global__ void __launch_bounds__(256) pack_a(
    const float* __restrict__ X, const float* __restrict__ gamma)
{
    const int fragid = blockIdx.x * 8 + (threadIdx.x >> 5);
    const int lane = threadIdx.x & 31;
    const int m16 = fragid >> 4, k16 = fragid & 15;
    const int row0 = (m16 << 4) + (lane >> 2);
    const int row1 = row0 + 8;
    const int kc = (k16 << 4) + ((lane & 3) << 1);

    float2 x00 = *(const float2*)(X + (size_t)row0 * DIM + kc);
    float2 x01 = *(const float2*)(X + (size_t)row0 * DIM + kc + 8);
    float2 x10 = *(const float2*)(X + (size_t)row1 * DIM + kc);
    float2 x11 = *(const float2*)(X + (size_t)row1 * DIM + kc + 8);
    if (LN) {
        float mu0 = g_mu[row0], rs0 = g_rstd[row0];
        float mu1 = g_mu[row1], rs1 = g_rstd[row1];
        float2 g0 = *(const float2*)(gamma + kc);
        float2 g1 = *(const float2*)(gamma + kc + 8);
        x00.x = (x00.x - mu0) * rs0 * g0.x; x00.y = (x00.y - mu0) * rs0 * g0.y;
        x01.x = (x01.x - mu0) * rs0 * g1.x; x01.y = (x01.y - mu0) * rs0 * g1.y;
        x10.x = (x10.x - mu1) * rs1 * g0.x; x10.y = (x10.y - mu1) * rs1 * g0.y;
        x11.x = (x11.x - mu1) * rs1 * g1.x; x11.y = (x11.y - mu1) * rs1 * g1.y;
    }
    uint4 h, l;
    h.x = bpack(bhi(x00.x), bhi(x00.y));
    h.y = bpack(bhi(x10.x), bhi(x10.y));
    h.z = bpack(bhi(x01.x), bhi(x01.y));
    h.w = bpack(bhi(x11.x), bhi(x11.y));
    l.x = bpack(x00.x - bhi(x00.x), x00.y - bhi(x00.y));
    l.y = bpack(x10.x - bhi(x10.x), x10.y - bhi(x10.y));
    l.z = bpack(x01.x - bhi(x01.x), x01.y - bhi(x01.y));
    l.w = bpack(x11.x - bhi(x11.x), x11.y - bhi(x11.y));
    g_fah[(size_t)fragid * 32 + lane] = h;
    g_fal[(size_t)fragid * 32 + lane] = l;
}

// ============================================================
// Pack B (weights, [K=256][N]) into mma B-fragment layout.
// One thread per (n8, k16, lane).
// ============================================================
__global__ void __launch_bounds__(256) pack_b(
    const float* __restrict__ W, uint2* __restrict__ Bh, uint2* __restrict__ Bl, int N)
{
    const int t = blockIdx.x * 256 + threadIdx.x;
    const int lane = t & 31;
    const int k16 = (t >> 5) & 15;
    const int n8 = t >> 9;
    const int k = (k16 << 4) + ((lane & 3) << 1);
    const int n = (n8 << 3) + (lane >> 2);
    float w0 = W[(size_t)k * N + n];
    float w1 = W[(size_t)(k + 1) * N + n];
    float w2 = W[(size_t)(k + 8) * N + n];
    float w3 = W[(size_t)(k + 9) * N + n];
    uint2 h, l;
    h.x = bpack(bhi(w0), bhi(w1));
    h.y = bpack(bhi(w2), bhi(w3));
    l.x = bpack(w0 - bhi(w0), w1 - bhi(w1));
    l.y = bpack(w2 - bhi(w2), w3 - bhi(w3));
    Bh[t] = h;
    Bl[t] = l;
}

// ============================================================
// Warp-MMA GEMM: CTA 128x128, warp 32x64, K=256.
// bf16 split: Ah*Bh + Ah*Bl + Al*Bh, fp32 accumulate.
// No smem, no syncthreads: frags pre-packed in gmem.
// ============================================================
__global__ void __launch_bounds__(256) gemm_mma(
    const uint4* __restrict__ FAh, const uint4* __restrict__ FAl,
    const uint2* __restrict__ FBh, const uint2* __restrict__ FBl,
    float* __restrict__ C, int N)
{
    const int lane = threadIdx.x & 31;
    const int wid = threadIdx.x >> 5;
    const int m16b = blockIdx.y * 8 + (wid & 3) * 2;
    const int n8b  = blockIdx.x * 16 + (wid >> 2) * 8;

    const uint4* pAh = FAh + (size_t)m16b * 16 * 32 + lane;
    const uint4* pAl = FAl + (size_t)m16b * 16 * 32 + lane;
    const uint2* pBh = FBh + (size_t)n8b * 16 * 32 + lane;
    const uint2* pBl = FBl + (size_t)n8b * 16 * 32 + lane;

    float acc[2][8][4];
#pragma unroll
    for (int i = 0; i < 2; i++)
#pragma unroll
        for (int j = 0; j < 8; j++)
#pragma unroll
            for (int r = 0; r < 4; r++) acc[i][j][r] = 0.f;

    uint4 ah[2][2], al[2][2];
    ah[0][0] = pAh[0]; ah[0][1] = pAh[16 * 32];
    al[0][0] = pAl[0]; al[0][1] = pAl[16 * 32];

#pragma unroll 2
    for (int kk = 0; kk < 16; kk++) {
        const int cur = kk & 1, nxt = cur ^ 1;
        uint2 bh[8], bl[8];
#pragma unroll
        for (int j = 0; j < 8; j++) {
            bh[j] = pBh[j * 512 + kk * 32];
            bl[j] = pBl[j * 512 + kk * 32];
        }
        if (kk < 15) {
            ah[nxt][0] = pAh[(kk + 1) * 32];
            ah[nxt][1] = pAh[(kk + 1) * 32 + 16 * 32];
            al[nxt][0] = pAl[(kk + 1) * 32];
            al[nxt][1] = pAl[(kk + 1) * 32 + 16 * 32];
        }
#pragma unroll
        for (int i = 0; i < 2; i++)
#pragma unroll
            for (int j = 0; j < 8; j++) {
                mma_bf16(acc[i][j], ah[cur][i], bh[j]);
                mma_bf16(acc[i][j], ah[cur][i], bl[j]);
                mma_bf16(acc[i][j], al[cur][i], bh[j]);
            }
    }

    // epilogue: per (i,j): rows lane/4 and lane/4+8, cols (lane&3)*2..+1
    const int r0 = (m16b << 4) + (lane >> 2);
    const int c0 = (n8b << 3) + ((lane & 3) << 1);
#pragma unroll
    for (int i = 0; i < 2; i++) {
        const size_t rowa = (size_t)(r0 + i * 16) * N;
        const size_t rowb = rowa + 8 * N;
#pragma unroll
        for (int j = 0; j < 8; j++) {
            *(float2*)(C + rowa + c0 + j * 8) = make_float2(acc[i][j][0], acc[i][j][1]);
            *(float2*)(C + rowb + c0 + j * 8) = make_float2(acc[i][j][2], acc[i][j][3]);
        }
    }
}

// ============================================================
// Attention: 2 (window,head) units per CTA, 128 threads.
// ============================================================
__global__ void __launch_bounds__(128) attn_kernel(
    const float* __restrict__ mem_kv, const float* __restrict__ bias_table)
{
    __shared__ float qs[2][WQ][36];
    __shared__ float ks[2][NKEY][DH];
    __shared__ float vs[2][NKEY][DH];
    __shared__ float bias_s[2][169];

    const int u = threadIdx.x >> 6;        // unit 0/1
    const int tid = threadIdx.x & 63;
    const int pair = blockIdx.x * 2 + u;
    const int b = pair >> 3;
    const int h = pair & 7;
    const size_t tok0 = (size_t)b * WQ;

    if (tid < 32) {
        int m = tid >> 3, c4 = tid & 7;
        *(float4*)&ks[u][m][c4 * 4] = *((const float4*)(mem_kv + (size_t)(h * NMEM + m) * DH) + c4);
        *(float4*)&vs[u][m][c4 * 4] = *((const float4*)(mem_kv + (size_t)(NHEADS * NMEM * DH)
                                                        + (size_t)(h * NMEM + m) * DH) + c4);
    }
    for (int f = tid; f < WQ * 8; f += 64) {
        int i = f >> 3, c4 = f & 7;
        const float* base = g_qkv + (tok0 + i) * NQKV + h * DH;
        *(float4*)&qs[u][i][c4 * 4]        = *((const float4*)base + c4);
        *(float4*)&ks[u][NMEM + i][c4 * 4] = *((const float4*)(base + 256) + c4);
        *(float4*)&vs[u][NMEM + i][c4 * 4] = *((const float4*)(base + 512) + c4);
    }
    for (int f = tid; f < 169; f += 64)
        bias_s[u][f] = bias_table[f * NHEADS + h];
    __syncthreads();

    if (tid < WQ) {
        const int i = tid;
        ull q2[16];
#pragma unroll
        for (int c4 = 0; c4 < 8; c4++) {
            ulonglong2 t = ((const ulonglong2*)&qs[u][i][0])[c4];
            q2[c4 * 2] = t.x; q2[c4 * 2 + 1] = t.y;
        }
        float sim[NKEY];
        const float scale = 0.17677669529663687f;
#pragma unroll
        for (int j = 0; j < NKEY; j++) {
            ull s2 = 0ull;
#pragma unroll
            for (int c4 = 0; c4 < 8; c4++) {
                ulonglong2 t = ((const ulonglong2*)&ks[u][j][0])[c4];
                s2 = ffma2(q2[c4 * 2], t.x, s2);
                s2 = ffma2(q2[c4 * 2 + 1], t.y, s2);
            }
            float lo, hi; upk2(s2, lo, hi);
            sim[j] = (lo + hi) * scale;
        }
        const int yi = i / 7, xi = i % 7;
#pragma unroll
        for (int j = 0; j < WQ; j++) {
            int yj = j / 7, xj = j % 7;
            sim[NMEM + j] += bias_s[u][(yi - yj + 6) * 13 + (xi - xj + 6)];
        }
        float mx = sim[0];
#pragma unroll
        for (int j = 1; j < NKEY; j++) mx = fmaxf(mx, sim[j]);
        float l = 0.f;
#pragma unroll
        for (int j = 0; j < NKEY; j++) { float p = __expf(sim[j] - mx); sim[j] = p; l += p; }
        float inv = 1.f / l;
        ull o2[16];
#pragma unroll
        for (int c = 0; c < 16; c++) o2[c] = 0ull;
#pragma unroll
        for (int j = 0; j < NKEY; j++) {
            ull p2 = pk2(sim[j], sim[j]);
#pragma unroll
            for (int c4 = 0; c4 < 8; c4++) {
                ulonglong2 t = ((const ulonglong2*)&vs[u][j][0])[c4];
                o2[c4 * 2]     = ffma2(p2, t.x, o2[c4 * 2]);
                o2[c4 * 2 + 1] = ffma2(p2, t.y, o2[c4 * 2 + 1]);
            }
        }
#pragma unroll
        for (int c4 = 0; c4 < 8; c4++) {
            float a, bx, c, d;
            upk2(o2[c4 * 2], a, bx);
            upk2(o2[c4 * 2 + 1], c, d);
            *(float4*)&qs[u][tid][c4 * 4] = make_float4(a * inv, bx * inv, c * inv, d * inv);
        }
    }
    __syncthreads();
    for (int f = tid; f < WQ * 8; f += 64) {
        int i = f >> 3, c4 = f & 7;
        *((float4*)(g_attn + (tok0 + i) * DIM + h * DH) + c4) = *(const float4*)&qs[u][i][c4 * 4];
    }
}

// ============================================================
extern "C" void kernel_launch(void* const* d_in, const int* in_sizes, int n_in,
                              void* d_out, int out_size) {
    const float* x          = (const float*)d_in[0];
    const float* gamma      = (const float*)d_in[1];
    const float* w_qkv      = (const float*)d_in[2];
    const float* mem_kv     = (const float*)d_in[3];
    const float* bias_table = (const float*)d_in[4];
    const float* w_out      = (const float*)d_in[5];
    float* out = (float*)d_out;

    float *qkv_p, *attn_p;
    cudaGetSymbolAddress((void**)&qkv_p,  g_qkv);
    cudaGetSymbolAddress((void**)&attn_p, g_attn);
    uint4 *fah, *fal;
    cudaGetSymbolAddress((void**)&fah, g_fah);
    cudaGetSymbolAddress((void**)&fal, g_fal);
    uint2 *fbh1, *fbl1, *fbh2, *fbl2;
    cudaGetSymbolAddress((void**)&fbh1, g_fbh1);
    cudaGetSymbolAddress((void**)&fbl1, g_fbl1);
    cudaGetSymbolAddress((void**)&fbh2, g_fbh2);
    cudaGetSymbolAddress((void**)&fbl2, g_fbl2);

    const int nfragA = (TOKENS / 16) * 16;          // 200704 frags

    ln_stats_kernel<<<TOKENS / 8, 256>>>(x);
    pack_b<<<(NQKV / 8) * 16 * 32 / 256, 256>>>(w_qkv, fbh1, fbl1, NQKV);
    pack_b<<<(DIM / 8) * 16 * 32 / 256, 256>>>(w_out, fbh2, fbl2, DIM);
    pack_a<true><<<nfragA / 8, 256>>>(x, gamma);
    gemm_mma<<<dim3(NQKV / 128, TOKENS / 128), 256>>>(fah, fal, fbh1, fbl1, qkv_p, NQKV);
    attn_kernel<<<NWIN * NHEADS / 2, 128>>>(mem_kv, bias_table);
    pack_a<false><<<nfragA / 8, 256>>>(attn_p, nullptr);
    gemm_mma<<<dim3(DIM / 128, TOKENS / 128), 256>>>(fah, fal, fbh2, fbl2, out, DIM);
}

// round 5
// speedup vs baseline: 2.6973x; 1.0974x over previous
#include <cuda_runtime.h>
#include <cuda_bf16.h>
#include <cstdint>

#define TOKENS 200704          // 16*16*16*49
#define DIM 256
#define NQKV 768
#define NWIN 4096
#define WQ 49
#define NKEY 53
#define NMEM 4
#define DH 32
#define NHEADS 8

typedef unsigned long long ull;

// ---- scratch (static device globals; no runtime allocation) ----
__device__ float g_qkv[(size_t)TOKENS * NQKV];        // 616 MB
__device__ float g_attn[(size_t)TOKENS * DIM];        // 205 MB
// fragment-major A: frag(m16,k16) -> 32 lanes x uint4
__device__ uint4 g_fah[(size_t)(TOKENS / 16) * 16 * 32];
__device__ uint4 g_fal[(size_t)(TOKENS / 16) * 16 * 32];
// fragment-major B: frag(n8,k16) -> 32 lanes x uint2
__device__ uint2 g_fbh1[(NQKV / 8) * 16 * 32];
__device__ uint2 g_fbl1[(NQKV / 8) * 16 * 32];
__device__ uint2 g_fbh2[(DIM / 8) * 16 * 32];
__device__ uint2 g_fbl2[(DIM / 8) * 16 * 32];

// ---- helpers ----
__device__ __forceinline__ uint32_t bpack(float x, float y) {
    __nv_bfloat162 t = __floats2bfloat162_rn(x, y);   // low half = x
    return *(uint32_t*)&t;
}
__device__ __forceinline__ float bhi(float x) {
    return __bfloat162float(__float2bfloat16(x));
}
__device__ __forceinline__ void mma_bf16(float* d, const uint4& a, const uint2& b) {
    asm volatile("mma.sync.aligned.m16n8k16.row.col.f32.bf16.bf16.f32 "
        "{%0,%1,%2,%3}, {%4,%5,%6,%7}, {%8,%9}, {%0,%1,%2,%3};"
        : "+f"(d[0]), "+f"(d[1]), "+f"(d[2]), "+f"(d[3])
        : "r"(a.x), "r"(a.y), "r"(a.z), "r"(a.w), "r"(b.x), "r"(b.y));
}
// packed fp32x2 (attention)
__device__ __forceinline__ ull pk2(float x, float y) {
    ull r; asm("mov.b64 %0, {%1, %2};" : "=l"(r) : "f"(x), "f"(y)); return r;
}
__device__ __forceinline__ void upk2(ull v, float& x, float& y) {
    asm("mov.b64 {%0, %1}, %2;" : "=f"(x), "=f"(y) : "l"(v));
}
__device__ __forceinline__ ull ffma2(ull a, ull b, ull c) {
    ull d; asm("fma.rn.f32x2 %0, %1, %2, %3;" : "=l"(d) : "l"(a), "l"(b), "l"(c)); return d;
}

// ============================================================
// Fused LayerNorm + A-fragment pack. CTA = 32 tokens.
// Phase 1: stats (warp per 4 tokens) -> smem.
// Phase 2: pack 32 frags (warp per 4 frags), x re-read hits L1.
// ============================================================
__global__ void __launch_bounds__(256) ln_pack_a(
    const float* __restrict__ X, const float* __restrict__ gamma)
{
    __shared__ float smu[32], srs[32];
    const int t0 = blockIdx.x * 32;
    const int w = threadIdx.x >> 5, lane = threadIdx.x & 31;

#pragma unroll
    for (int i = 0; i < 4; i++) {
        int tok = t0 + w * 4 + i;
        const float4* row = (const float4*)(X + (size_t)tok * DIM);
        float4 v0 = row[lane * 2], v1 = row[lane * 2 + 1];
        float s  = (v0.x + v0.y) + (v0.z + v0.w) + (v1.x + v1.y) + (v1.z + v1.w);
        float ss = v0.x * v0.x + v0.y * v0.y + v0.z * v0.z + v0.w * v0.w
                 + v1.x * v1.x + v1.y * v1.y + v1.z * v1.z + v1.w * v1.w;
#pragma unroll
        for (int o = 16; o; o >>= 1) {
            s  += __shfl_xor_sync(0xffffffffu, s, o);
            ss += __shfl_xor_sync(0xffffffffu, ss, o);
        }
        if (lane == 0) {
            float mu = s * (1.f / DIM);
            float var = fmaxf(ss * (1.f / DIM) - mu * mu, 0.f);
            smu[w * 4 + i] = mu;
            srs[w * 4 + i] = rsqrtf(var + 1e-5f);
        }
    }
    __syncthreads();

#pragma unroll
    for (int fi = 0; fi < 4; fi++) {
        const int f = w * 4 + fi;             // local frag 0..31
        const int lm = f >> 4, k16 = f & 15;
        const int rl0 = lm * 16 + (lane >> 2);
        const int rl1 = rl0 + 8;
        const int row0 = t0 + rl0, row1 = t0 + rl1;
        const int kc = (k16 << 4) + ((lane & 3) << 1);

        float2 x00 = *(const float2*)(X + (size_t)row0 * DIM + kc);
        float2 x01 = *(const float2*)(X + (size_t)row0 * DIM + kc + 8);
        float2 x10 = *(const float2*)(X + (size_t)row1 * DIM + kc);
        float2 x11 = *(const float2*)(X + (size_t)row1 * DIM + kc + 8);
        float mu0 = smu[rl0], rs0 = srs[rl0];
        float mu1 = smu[rl1], rs1 = srs[rl1];
        float2 g0 = *(const float2*)(gamma + kc);
        float2 g1 = *(const float2*)(gamma + kc + 8);
        x00.x = (x00.x - mu0) * rs0 * g0.x; x00.y = (x00.y - mu0) * rs0 * g0.y;
        x01.x = (x01.x - mu0) * rs0 * g1.x; x01.y = (x01.y - mu0) * rs0 * g1.y;
        x10.x = (x10.x - mu1) * rs1 * g0.x; x10.y = (x10.y - mu1) * rs1 * g0.y;
        x11.x = (x11.x - mu1) * rs1 * g1.x; x11.y = (x11.y - mu1) * rs1 * g1.y;

        uint4 h, l;
        h.x = bpack(bhi(x00.x), bhi(x00.y));
        h.y = bpack(bhi(x10.x), bhi(x10.y));
        h.z = bpack(bhi(x01.x), bhi(x01.y));
        h.w = bpack(bhi(x11.x), bhi(x11.y));
        l.x = bpack(x00.x - bhi(x00.x), x00.y - bhi(x00.y));
        l.y = bpack(x10.x - bhi(x10.x), x10.y - bhi(x10.y));
        l.z = bpack(x01.x - bhi(x01.x), x01.y - bhi(x01.y));
        l.w = bpack(x11.x - bhi(x11.x), x11.y - bhi(x11.y));
        const size_t fragid = (size_t)(t0 / 16 + lm) * 16 + k16;
        g_fah[fragid * 32 + lane] = h;
        g_fal[fragid * 32 + lane] = l;
    }
}

// ============================================================
// Pack A from plain fp32 matrix (attention output), no LN.
// ============================================================
__global__ void __launch_bounds__(256) pack_a_plain(const float* __restrict__ X) {
    const int fragid = blockIdx.x * 8 + (threadIdx.x >> 5);
    const int lane = threadIdx.x & 31;
    const int m16 = fragid >> 4, k16 = fragid & 15;
    const int row0 = (m16 << 4) + (lane >> 2);
    const int row1 = row0 + 8;
    const int kc = (k16 << 4) + ((lane & 3) << 1);

    float2 x00 = *(const float2*)(X + (size_t)row0 * DIM + kc);
    float2 x01 = *(const float2*)(X + (size_t)row0 * DIM + kc + 8);
    float2 x10 = *(const float2*)(X + (size_t)row1 * DIM + kc);
    float2 x11 = *(const float2*)(X + (size_t)row1 * DIM + kc + 8);
    uint4 h, l;
    h.x = bpack(bhi(x00.x), bhi(x00.y));
    h.y = bpack(bhi(x10.x), bhi(x10.y));
    h.z = bpack(bhi(x01.x), bhi(x01.y));
    h.w = bpack(bhi(x11.x), bhi(x11.y));
    l.x = bpack(x00.x - bhi(x00.x), x00.y - bhi(x00.y));
    l.y = bpack(x10.x - bhi(x10.x), x10.y - bhi(x10.y));
    l.z = bpack(x01.x - bhi(x01.x), x01.y - bhi(x01.y));
    l.w = bpack(x11.x - bhi(x11.x), x11.y - bhi(x11.y));
    g_fah[(size_t)fragid * 32 + lane] = h;
    g_fal[(size_t)fragid * 32 + lane] = l;
}

// ============================================================
// Pack B (weights, [K=256][N]) into mma B-fragment layout.
// ============================================================
__global__ void __launch_bounds__(256) pack_b(
    const float* __restrict__ W, uint2* __restrict__ Bh, uint2* __restrict__ Bl, int N)
{
    const int t = blockIdx.x * 256 + threadIdx.x;
    const int lane = t & 31;
    const int k16 = (t >> 5) & 15;
    const int n8 = t >> 9;
    const int k = (k16 << 4) + ((lane & 3) << 1);
    const int n = (n8 << 3) + (lane >> 2);
    float w0 = W[(size_t)k * N + n];
    float w1 = W[(size_t)(k + 1) * N + n];
    float w2 = W[(size_t)(k + 8) * N + n];
    float w3 = W[(size_t)(k + 9) * N + n];
    uint2 h, l;
    h.x = bpack(bhi(w0), bhi(w1));
    h.y = bpack(bhi(w2), bhi(w3));
    l.x = bpack(w0 - bhi(w0), w1 - bhi(w1));
    l.y = bpack(w2 - bhi(w2), w3 - bhi(w3));
    Bh[t] = h;
    Bl[t] = l;
}

// ============================================================
// Warp-MMA GEMM v2: CTA 128x128, 4 warps of 64x64, K=256.
// bf16 split: Ah*Bh + Ah*Bl + Al*Bh, fp32 accumulate.
// 24 LDG per 96 HMMA per k-step (LDG-dispatch relief).
// ============================================================
__global__ void __launch_bounds__(128, 2) gemm_mma(
    const uint4* __restrict__ FAh, const uint4* __restrict__ FAl,
    const uint2* __restrict__ FBh, const uint2* __restrict__ FBl,
    float* __restrict__ C, int N)
{
    const int lane = threadIdx.x & 31;
    const int wid = threadIdx.x >> 5;
    const int m16b = blockIdx.y * 8 + (wid & 1) * 4;   // 4 m16-frags per warp
    const int n8b  = blockIdx.x * 16 + (wid >> 1) * 8; // 8 n8-frags per warp

    const uint4* pAh = FAh + (size_t)m16b * 16 * 32 + lane;
    const uint4* pAl = FAl + (size_t)m16b * 16 * 32 + lane;
    const uint2* pBh = FBh + (size_t)n8b * 16 * 32 + lane;
    const uint2* pBl = FBl + (size_t)n8b * 16 * 32 + lane;

    float acc[4][8][4];
#pragma unroll
    for (int i = 0; i < 4; i++)
#pragma unroll
        for (int j = 0; j < 8; j++)
#pragma unroll
            for (int r = 0; r < 4; r++) acc[i][j][r] = 0.f;

#pragma unroll 2
    for (int kk = 0; kk < 16; kk++) {
        uint2 bh[8], bl[8];
#pragma unroll
        for (int j = 0; j < 8; j++) {
            bh[j] = pBh[(j * 16 + kk) * 32];
            bl[j] = pBl[(j * 16 + kk) * 32];
        }
#pragma unroll
        for (int i = 0; i < 4; i++) {
            uint4 ah = pAh[(i * 16 + kk) * 32];
            uint4 al = pAl[(i * 16 + kk) * 32];
#pragma unroll
            for (int j = 0; j < 8; j++) {
                mma_bf16(acc[i][j], ah, bh[j]);
                mma_bf16(acc[i][j], ah, bl[j]);
                mma_bf16(acc[i][j], al, bh[j]);
            }
        }
    }

    const int r0 = (m16b << 4) + (lane >> 2);
    const int c0 = (n8b << 3) + ((lane & 3) << 1);
#pragma unroll
    for (int i = 0; i < 4; i++) {
        const size_t rowa = (size_t)(r0 + i * 16) * N;
        const size_t rowb = rowa + 8 * N;
#pragma unroll
        for (int j = 0; j < 8; j++) {
            *(float2*)(C + rowa + c0 + j * 8) = make_float2(acc[i][j][0], acc[i][j][1]);
            *(float2*)(C + rowb + c0 + j * 8) = make_float2(acc[i][j][2], acc[i][j][3]);
        }
    }
}

// ============================================================
// Attention: 2 (window,head) units per CTA, 128 threads.
// ============================================================
__global__ void __launch_bounds__(128) attn_kernel(
    const float* __restrict__ mem_kv, const float* __restrict__ bias_table)
{
    __shared__ float qs[2][WQ][36];
    __shared__ float ks[2][NKEY][DH];
    __shared__ float vs[2][NKEY][DH];
    __shared__ float bias_s[2][169];

    const int u = threadIdx.x >> 6;
    const int tid = threadIdx.x & 63;
    const int pair = blockIdx.x * 2 + u;
    const int b = pair >> 3;
    const int h = pair & 7;
    const size_t tok0 = (size_t)b * WQ;

    if (tid < 32) {
        int m = tid >> 3, c4 = tid & 7;
        *(float4*)&ks[u][m][c4 * 4] = *((const float4*)(mem_kv + (size_t)(h * NMEM + m) * DH) + c4);
        *(float4*)&vs[u][m][c4 * 4] = *((const float4*)(mem_kv + (size_t)(NHEADS * NMEM * DH)
                                                        + (size_t)(h * NMEM + m) * DH) + c4);
    }
    for (int f = tid; f < WQ * 8; f += 64) {
        int i = f >> 3, c4 = f & 7;
        const float* base = g_qkv + (tok0 + i) * NQKV + h * DH;
        *(float4*)&qs[u][i][c4 * 4]        = *((const float4*)base + c4);
        *(float4*)&ks[u][NMEM + i][c4 * 4] = *((const float4*)(base + 256) + c4);
        *(float4*)&vs[u][NMEM + i][c4 * 4] = *((const float4*)(base + 512) + c4);
    }
    for (int f = tid; f < 169; f += 64)
        bias_s[u][f] = bias_table[f * NHEADS + h];
    __syncthreads();

    if (tid < WQ) {
        const int i = tid;
        ull q2[16];
#pragma unroll
        for (int c4 = 0; c4 < 8; c4++) {
            ulonglong2 t = ((const ulonglong2*)&qs[u][i][0])[c4];
            q2[c4 * 2] = t.x; q2[c4 * 2 + 1] = t.y;
        }
        float sim[NKEY];
        const float scale = 0.17677669529663687f;
#pragma unroll
        for (int j = 0; j < NKEY; j++) {
            ull s2 = 0ull;
#pragma unroll
            for (int c4 = 0; c4 < 8; c4++) {
                ulonglong2 t = ((const ulonglong2*)&ks[u][j][0])[c4];
                s2 = ffma2(q2[c4 * 2], t.x, s2);
                s2 = ffma2(q2[c4 * 2 + 1], t.y, s2);
            }
            float lo, hi; upk2(s2, lo, hi);
            sim[j] = (lo + hi) * scale;
        }
        const int yi = i / 7, xi = i % 7;
#pragma unroll
        for (int j = 0; j < WQ; j++) {
            int yj = j / 7, xj = j % 7;
            sim[NMEM + j] += bias_s[u][(yi - yj + 6) * 13 + (xi - xj + 6)];
        }
        float mx = sim[0];
#pragma unroll
        for (int j = 1; j < NKEY; j++) mx = fmaxf(mx, sim[j]);
        float l = 0.f;
#pragma unroll
        for (int j = 0; j < NKEY; j++) { float p = __expf(sim[j] - mx); sim[j] = p; l += p; }
        float inv = 1.f / l;
        ull o2[16];
#pragma unroll
        for (int c = 0; c < 16; c++) o2[c] = 0ull;
#pragma unroll
        for (int j = 0; j < NKEY; j++) {
            ull p2 = pk2(sim[j], sim[j]);
#pragma unroll
            for (int c4 = 0; c4 < 8; c4++) {
                ulonglong2 t = ((const ulonglong2*)&vs[u][j][0])[c4];
                o2[c4 * 2]     = ffma2(p2, t.x, o2[c4 * 2]);
                o2[c4 * 2 + 1] = ffma2(p2, t.y, o2[c4 * 2 + 1]);
            }
        }
#pragma unroll
        for (int c4 = 0; c4 < 8; c4++) {
            float a, bx, c, d;
            upk2(o2[c4 * 2], a, bx);
            upk2(o2[c4 * 2 + 1], c, d);
            *(float4*)&qs[u][tid][c4 * 4] = make_float4(a * inv, bx * inv, c * inv, d * inv);
        }
    }
    __syncthreads();
    for (int f = tid; f < WQ * 8; f += 64) {
        int i = f >> 3, c4 = f & 7;
        *((float4*)(g_attn + (tok0 + i) * DIM + h * DH) + c4) = *(const float4*)&qs[u][i][c4 * 4];
    }
}

// ============================================================
extern "C" void kernel_launch(void* const* d_in, const int* in_sizes, int n_in,
                              void* d_out, int out_size) {
    const float* x          = (const float*)d_in[0];
    const float* gamma      = (const float*)d_in[1];
    const float* w_qkv      = (const float*)d_in[2];
    const float* mem_kv     = (const float*)d_in[3];
    const float* bias_table = (const float*)d_in[4];
    const float* w_out      = (const float*)d_in[5];
    float* out = (float*)d_out;

    float *qkv_p, *attn_p;
    cudaGetSymbolAddress((void**)&qkv_p,  g_qkv);
    cudaGetSymbolAddress((void**)&attn_p, g_attn);
    uint4 *fah, *fal;
    cudaGetSymbolAddress((void**)&fah, g_fah);
    cudaGetSymbolAddress((void**)&fal, g_fal);
    uint2 *fbh1, *fbl1, *fbh2, *fbl2;
    cudaGetSymbolAddress((void**)&fbh1, g_fbh1);
    cudaGetSymbolAddress((void**)&fbl1, g_fbl1);
    cudaGetSymbolAddress((void**)&fbh2, g_fbh2);
    cudaGetSymbolAddress((void**)&fbl2, g_fbl2);

    pack_b<<<(NQKV / 8) * 16 * 32 / 256, 256>>>(w_qkv, fbh1, fbl1, NQKV);
    pack_b<<<(DIM / 8) * 16 * 32 / 256, 256>>>(w_out, fbh2, fbl2, DIM);
    ln_pack_a<<<TOKENS / 32, 256>>>(x, gamma);
    gemm_mma<<<dim3(NQKV / 128, TOKENS / 128), 128>>>(fah, fal, fbh1, fbl1, qkv_p, NQKV);
    attn_kernel<<<NWIN * NHEADS / 2, 128>>>(mem_kv, bias_table);
    pack_a_plain<<<(TOKENS / 16) * 16 / 8, 256>>>(attn_p);
    gemm_mma<<<dim3(DIM / 128, TOKENS / 128), 128>>>(fah, fal, fbh2, fbl2, out, DIM);
}

// round 6
// speedup vs baseline: 2.7136x; 1.0060x over previous
#include <cuda_runtime.h>
#include <cuda_bf16.h>
#include <cstdint>

#define TOKENS 200704          // 16*16*16*49
#define DIM 256
#define NQKV 768
#define NWIN 4096
#define WQ 49
#define NKEY 53
#define NMEM 4
#define DH 32
#define NHEADS 8

typedef unsigned long long ull;

// ---- scratch (static device globals; no runtime allocation) ----
__device__ float g_qkv[(size_t)TOKENS * NQKV];        // 616 MB
// fragment-major A: frag(m16,k16) -> 32 lanes x uint4
__device__ uint4 g_fah[(size_t)(TOKENS / 16) * 16 * 32];
__device__ uint4 g_fal[(size_t)(TOKENS / 16) * 16 * 32];
// fragment-major B: frag(n8,k16) -> 32 lanes x uint2
__device__ uint2 g_fbh1[(NQKV / 8) * 16 * 32];
__device__ uint2 g_fbl1[(NQKV / 8) * 16 * 32];
__device__ uint2 g_fbh2[(DIM / 8) * 16 * 32];
__device__ uint2 g_fbl2[(DIM / 8) * 16 * 32];

// ---- helpers ----
__device__ __forceinline__ uint32_t bpack(float x, float y) {
    __nv_bfloat162 t = __floats2bfloat162_rn(x, y);   // low half = x
    return *(uint32_t*)&t;
}
__device__ __forceinline__ float bhi(float x) {
    return __bfloat162float(__float2bfloat16(x));
}
// split a pair to bf16 hi-word + lo-word (hi extracted from the packed word)
__device__ __forceinline__ void split2(float x, float y, uint32_t& hw, uint32_t& lw) {
    hw = bpack(x, y);
    float hx = __uint_as_float(hw << 16);
    float hy = __uint_as_float(hw & 0xffff0000u);
    lw = bpack(x - hx, y - hy);
}
__device__ __forceinline__ void mma_bf16(float* d, const uint4& a, const uint2& b) {
    asm volatile("mma.sync.aligned.m16n8k16.row.col.f32.bf16.bf16.f32 "
        "{%0,%1,%2,%3}, {%4,%5,%6,%7}, {%8,%9}, {%0,%1,%2,%3};"
        : "+f"(d[0]), "+f"(d[1]), "+f"(d[2]), "+f"(d[3])
        : "r"(a.x), "r"(a.y), "r"(a.z), "r"(a.w), "r"(b.x), "r"(b.y));
}
// packed fp32x2 (attention)
__device__ __forceinline__ ull pk2(float x, float y) {
    ull r; asm("mov.b64 %0, {%1, %2};" : "=l"(r) : "f"(x), "f"(y)); return r;
}
__device__ __forceinline__ void upk2(ull v, float& x, float& y) {
    asm("mov.b64 {%0, %1}, %2;" : "=f"(x), "=f"(y) : "l"(v));
}
__device__ __forceinline__ ull ffma2(ull a, ull b, ull c) {
    ull d; asm("fma.rn.f32x2 %0, %1, %2, %3;" : "=l"(d) : "l"(a), "l"(b), "l"(c)); return d;
}

// ============================================================
// Fused LayerNorm + A-fragment pack. CTA = 32 tokens.
// ============================================================
__global__ void __launch_bounds__(256) ln_pack_a(
    const float* __restrict__ X, const float* __restrict__ gamma)
{
    __shared__ float smu[32], srs[32];
    const int t0 = blockIdx.x * 32;
    const int w = threadIdx.x >> 5, lane = threadIdx.x & 31;

#pragma unroll
    for (int i = 0; i < 4; i++) {
        int tok = t0 + w * 4 + i;
        const float4* row = (const float4*)(X + (size_t)tok * DIM);
        float4 v0 = row[lane * 2], v1 = row[lane * 2 + 1];
        float s  = (v0.x + v0.y) + (v0.z + v0.w) + (v1.x + v1.y) + (v1.z + v1.w);
        float ss = v0.x * v0.x + v0.y * v0.y + v0.z * v0.z + v0.w * v0.w
                 + v1.x * v1.x + v1.y * v1.y + v1.z * v1.z + v1.w * v1.w;
#pragma unroll
        for (int o = 16; o; o >>= 1) {
            s  += __shfl_xor_sync(0xffffffffu, s, o);
            ss += __shfl_xor_sync(0xffffffffu, ss, o);
        }
        if (lane == 0) {
            float mu = s * (1.f / DIM);
            float var = fmaxf(ss * (1.f / DIM) - mu * mu, 0.f);
            smu[w * 4 + i] = mu;
            srs[w * 4 + i] = rsqrtf(var + 1e-5f);
        }
    }
    __syncthreads();

#pragma unroll
    for (int fi = 0; fi < 4; fi++) {
        const int f = w * 4 + fi;
        const int lm = f >> 4, k16 = f & 15;
        const int rl0 = lm * 16 + (lane >> 2);
        const int rl1 = rl0 + 8;
        const int row0 = t0 + rl0, row1 = t0 + rl1;
        const int kc = (k16 << 4) + ((lane & 3) << 1);

        float2 x00 = *(const float2*)(X + (size_t)row0 * DIM + kc);
        float2 x01 = *(const float2*)(X + (size_t)row0 * DIM + kc + 8);
        float2 x10 = *(const float2*)(X + (size_t)row1 * DIM + kc);
        float2 x11 = *(const float2*)(X + (size_t)row1 * DIM + kc + 8);
        float mu0 = smu[rl0], rs0 = srs[rl0];
        float mu1 = smu[rl1], rs1 = srs[rl1];
        float2 g0 = *(const float2*)(gamma + kc);
        float2 g1 = *(const float2*)(gamma + kc + 8);
        x00.x = (x00.x - mu0) * rs0 * g0.x; x00.y = (x00.y - mu0) * rs0 * g0.y;
        x01.x = (x01.x - mu0) * rs0 * g1.x; x01.y = (x01.y - mu0) * rs0 * g1.y;
        x10.x = (x10.x - mu1) * rs1 * g0.x; x10.y = (x10.y - mu1) * rs1 * g0.y;
        x11.x = (x11.x - mu1) * rs1 * g1.x; x11.y = (x11.y - mu1) * rs1 * g1.y;

        uint4 h, l;
        split2(x00.x, x00.y, h.x, l.x);
        split2(x10.x, x10.y, h.y, l.y);
        split2(x01.x, x01.y, h.z, l.z);
        split2(x11.x, x11.y, h.w, l.w);
        const size_t fragid = (size_t)(t0 / 16 + lm) * 16 + k16;
        g_fah[fragid * 32 + lane] = h;
        g_fal[fragid * 32 + lane] = l;
    }
}

// ============================================================
// Pack B (weights, [K=256][N]) into mma B-fragment layout.
// ============================================================
__global__ void __launch_bounds__(256) pack_b(
    const float* __restrict__ W, uint2* __restrict__ Bh, uint2* __restrict__ Bl, int N)
{
    const int t = blockIdx.x * 256 + threadIdx.x;
    const int lane = t & 31;
    const int k16 = (t >> 5) & 15;
    const int n8 = t >> 9;
    const int k = (k16 << 4) + ((lane & 3) << 1);
    const int n = (n8 << 3) + (lane >> 2);
    float w0 = W[(size_t)k * N + n];
    float w1 = W[(size_t)(k + 1) * N + n];
    float w2 = W[(size_t)(k + 8) * N + n];
    float w3 = W[(size_t)(k + 9) * N + n];
    uint2 h, l;
    split2(w0, w1, h.x, l.x);
    split2(w2, w3, h.y, l.y);
    Bh[t] = h;
    Bl[t] = l;
}

// ============================================================
// Warp-MMA GEMM: CTA 128x128, 4 warps of 64x64, K=256.
// ============================================================
__global__ void __launch_bounds__(128, 2) gemm_mma(
    const uint4* __restrict__ FAh, const uint4* __restrict__ FAl,
    const uint2* __restrict__ FBh, const uint2* __restrict__ FBl,
    float* __restrict__ C, int N)
{
    const int lane = threadIdx.x & 31;
    const int wid = threadIdx.x >> 5;
    const int m16b = blockIdx.y * 8 + (wid & 1) * 4;
    const int n8b  = blockIdx.x * 16 + (wid >> 1) * 8;

    const uint4* pAh = FAh + (size_t)m16b * 16 * 32 + lane;
    const uint4* pAl = FAl + (size_t)m16b * 16 * 32 + lane;
    const uint2* pBh = FBh + (size_t)n8b * 16 * 32 + lane;
    const uint2* pBl = FBl + (size_t)n8b * 16 * 32 + lane;

    float acc[4][8][4];
#pragma unroll
    for (int i = 0; i < 4; i++)
#pragma unroll
        for (int j = 0; j < 8; j++)
#pragma unroll
            for (int r = 0; r < 4; r++) acc[i][j][r] = 0.f;

#pragma unroll 2
    for (int kk = 0; kk < 16; kk++) {
        uint2 bh[8], bl[8];
#pragma unroll
        for (int j = 0; j < 8; j++) {
            bh[j] = pBh[(j * 16 + kk) * 32];
            bl[j] = pBl[(j * 16 + kk) * 32];
        }
#pragma unroll
        for (int i = 0; i < 4; i++) {
            uint4 ah = pAh[(i * 16 + kk) * 32];
            uint4 al = pAl[(i * 16 + kk) * 32];
#pragma unroll
            for (int j = 0; j < 8; j++) {
                mma_bf16(acc[i][j], ah, bh[j]);
                mma_bf16(acc[i][j], ah, bl[j]);
                mma_bf16(acc[i][j], al, bh[j]);
            }
        }
    }

    const int r0 = (m16b << 4) + (lane >> 2);
    const int c0 = (n8b << 3) + ((lane & 3) << 1);
#pragma unroll
    for (int i = 0; i < 4; i++) {
        const size_t rowa = (size_t)(r0 + i * 16) * N;
        const size_t rowb = rowa + 8 * N;
#pragma unroll
        for (int j = 0; j < 8; j++) {
            *(float2*)(C + rowa + c0 + j * 8) = make_float2(acc[i][j][0], acc[i][j][1]);
            *(float2*)(C + rowb + c0 + j * 8) = make_float2(acc[i][j][2], acc[i][j][3]);
        }
    }
}

// ============================================================
// Attention v3: 2 (window,head) units per 128-thr CTA.
// q loaded per-thread from gmem; k/v/bias in smem (28.5KB);
// output split to bf16 hi/lo and written DIRECTLY as A-frag words.
// ============================================================
__global__ void __launch_bounds__(128) attn_kernel(
    const float* __restrict__ mem_kv, const float* __restrict__ bias_table)
{
    __shared__ float ks[2][NKEY][DH];
    __shared__ float vs[2][NKEY][DH];
    __shared__ float bias_s[2][169];

    const int u = threadIdx.x >> 6;
    const int tid = threadIdx.x & 63;
    const int pair = blockIdx.x * 2 + u;
    const int b = pair >> 3;
    const int h = pair & 7;
    const size_t tok0 = (size_t)b * WQ;

    if (tid < 32) {
        int m = tid >> 3, c4 = tid & 7;
        *(float4*)&ks[u][m][c4 * 4] = *((const float4*)(mem_kv + (size_t)(h * NMEM + m) * DH) + c4);
        *(float4*)&vs[u][m][c4 * 4] = *((const float4*)(mem_kv + (size_t)(NHEADS * NMEM * DH)
                                                        + (size_t)(h * NMEM + m) * DH) + c4);
    }
    for (int f = tid; f < WQ * 8; f += 64) {
        int i = f >> 3, c4 = f & 7;
        const float* base = g_qkv + (tok0 + i) * NQKV + h * DH;
        *(float4*)&ks[u][NMEM + i][c4 * 4] = *((const float4*)(base + 256) + c4);
        *(float4*)&vs[u][NMEM + i][c4 * 4] = *((const float4*)(base + 512) + c4);
    }
    for (int f = tid; f < 169; f += 64)
        bias_s[u][f] = bias_table[f * NHEADS + h];
    __syncthreads();

    if (tid < WQ) {
        const int i = tid;
        const size_t tok = tok0 + i;
        // q row straight from gmem (fp32 pairs as packed f32x2)
        const ulonglong2* qp = (const ulonglong2*)(g_qkv + tok * NQKV + h * DH);
        ull q2[16];
#pragma unroll
        for (int c4 = 0; c4 < 8; c4++) {
            ulonglong2 t = qp[c4];
            q2[c4 * 2] = t.x; q2[c4 * 2 + 1] = t.y;
        }
        float sim[NKEY];
        const float scale = 0.17677669529663687f;
#pragma unroll
        for (int j = 0; j < NKEY; j++) {
            ull s2 = 0ull;
#pragma unroll
            for (int c4 = 0; c4 < 8; c4++) {
                ulonglong2 t = ((const ulonglong2*)&ks[u][j][0])[c4];
                s2 = ffma2(q2[c4 * 2], t.x, s2);
                s2 = ffma2(q2[c4 * 2 + 1], t.y, s2);
            }
            float lo, hi; upk2(s2, lo, hi);
            sim[j] = (lo + hi) * scale;
        }
        const int yi = i / 7, xi = i % 7;
#pragma unroll
        for (int j = 0; j < WQ; j++) {
            int yj = j / 7, xj = j % 7;
            sim[NMEM + j] += bias_s[u][(yi - yj + 6) * 13 + (xi - xj + 6)];
        }
        float mx = sim[0];
#pragma unroll
        for (int j = 1; j < NKEY; j++) mx = fmaxf(mx, sim[j]);
        float l = 0.f;
#pragma unroll
        for (int j = 0; j < NKEY; j++) { float p = __expf(sim[j] - mx); sim[j] = p; l += p; }
        float inv = 1.f / l;
        ull o2[16];
#pragma unroll
        for (int c = 0; c < 16; c++) o2[c] = 0ull;
#pragma unroll
        for (int j = 0; j < NKEY; j++) {
            ull p2 = pk2(sim[j], sim[j]);
#pragma unroll
            for (int c4 = 0; c4 < 8; c4++) {
                ulonglong2 t = ((const ulonglong2*)&vs[u][j][0])[c4];
                o2[c4 * 2]     = ffma2(p2, t.x, o2[c4 * 2]);
                o2[c4 * 2 + 1] = ffma2(p2, t.y, o2[c4 * 2 + 1]);
            }
        }
        float outv[32];
#pragma unroll
        for (int c = 0; c < 16; c++) {
            float lo, hi; upk2(o2[c], lo, hi);
            outv[2 * c] = lo * inv; outv[2 * c + 1] = hi * inv;
        }
        // --- direct A-fragment word stores ---
        const int r = (int)(tok & 15);
        const size_t m16 = tok >> 4;
        const int ybit = (r < 8) ? 0 : 1;       // comp x/y vs z/w select
#pragma unroll
        for (int c16 = 0; c16 < 2; c16++) {
            const size_t fbase = (m16 * 16 + 2 * h + c16) * 32;
#pragma unroll
            for (int lw = 0; lw < 4; lw++) {
                const int lane_t = (r & 7) * 4 + lw;
                uint32_t* wh = (uint32_t*)(g_fah + fbase + lane_t);
                uint32_t* wl = (uint32_t*)(g_fal + fbase + lane_t);
                uint32_t hw0, lw0, hw1, lw1;
                split2(outv[c16 * 16 + lw * 2],     outv[c16 * 16 + lw * 2 + 1], hw0, lw0);
                split2(outv[c16 * 16 + lw * 2 + 8], outv[c16 * 16 + lw * 2 + 9], hw1, lw1);
                wh[ybit]     = hw0;   // comp x or y
                wh[ybit + 2] = hw1;   // comp z or w
                wl[ybit]     = lw0;
                wl[ybit + 2] = lw1;
            }
        }
    }
}

// ============================================================
extern "C" void kernel_launch(void* const* d_in, const int* in_sizes, int n_in,
                              void* d_out, int out_size) {
    const float* x          = (const float*)d_in[0];
    const float* gamma      = (const float*)d_in[1];
    const float* w_qkv      = (const float*)d_in[2];
    const float* mem_kv     = (const float*)d_in[3];
    const float* bias_table = (const float*)d_in[4];
    const float* w_out      = (const float*)d_in[5];
    float* out = (float*)d_out;

    float* qkv_p;
    cudaGetSymbolAddress((void**)&qkv_p, g_qkv);
    uint4 *fah, *fal;
    cudaGetSymbolAddress((void**)&fah, g_fah);
    cudaGetSymbolAddress((void**)&fal, g_fal);
    uint2 *fbh1, *fbl1, *fbh2, *fbl2;
    cudaGetSymbolAddress((void**)&fbh1, g_fbh1);
    cudaGetSymbolAddress((void**)&fbl1, g_fbl1);
    cudaGetSymbolAddress((void**)&fbh2, g_fbh2);
    cudaGetSymbolAddress((void**)&fbl2, g_fbl2);

    pack_b<<<(NQKV / 8) * 16 * 32 / 256, 256>>>(w_qkv, fbh1, fbl1, NQKV);
    pack_b<<<(DIM / 8) * 16 * 32 / 256, 256>>>(w_out, fbh2, fbl2, DIM);
    ln_pack_a<<<TOKENS / 32, 256>>>(x, gamma);
    gemm_mma<<<dim3(NQKV / 128, TOKENS / 128), 128>>>(fah, fal, fbh1, fbl1, qkv_p, NQKV);
    attn_kernel<<<NWIN * NHEADS / 2, 128>>>(mem_kv, bias_table);
    gemm_mma<<<dim3(DIM / 128, TOKENS / 128), 128>>>(fah, fal, fbh2, fbl2, out, DIM);
}

// round 7
// speedup vs baseline: 2.7225x; 1.0033x over previous
#include <cuda_runtime.h>
#include <cuda_bf16.h>
#include <cstdint>

#define TOKENS 200704          // 16*16*16*49
#define DIM 256
#define NQKV 768
#define NWIN 4096
#define WQ 49
#define NKEY 53
#define NMEM 4
#define DH 32
#define NHEADS 8

typedef unsigned long long ull;

// ---- scratch (static device globals; no runtime allocation) ----
__device__ float g_qkv[(size_t)TOKENS * NQKV];        // 616 MB
// fragment-major A: frag(m16,k16) -> 32 lanes x uint4
__device__ uint4 g_fah[(size_t)(TOKENS / 16) * 16 * 32];
__device__ uint4 g_fal[(size_t)(TOKENS / 16) * 16 * 32];
// fragment-major B: frag(n8,k16) -> 32 lanes x uint2
__device__ uint2 g_fbh1[(NQKV / 8) * 16 * 32];
__device__ uint2 g_fbl1[(NQKV / 8) * 16 * 32];
__device__ uint2 g_fbh2[(DIM / 8) * 16 * 32];
__device__ uint2 g_fbl2[(DIM / 8) * 16 * 32];

// ---- helpers ----
__device__ __forceinline__ uint32_t bpack(float x, float y) {
    __nv_bfloat162 t = __floats2bfloat162_rn(x, y);   // low half = x
    return *(uint32_t*)&t;
}
__device__ __forceinline__ void split2(float x, float y, uint32_t& hw, uint32_t& lw) {
    hw = bpack(x, y);
    float hx = __uint_as_float(hw << 16);
    float hy = __uint_as_float(hw & 0xffff0000u);
    lw = bpack(x - hx, y - hy);
}
__device__ __forceinline__ void mma_bf16(float* d, const uint4& a, const uint2& b) {
    asm volatile("mma.sync.aligned.m16n8k16.row.col.f32.bf16.bf16.f32 "
        "{%0,%1,%2,%3}, {%4,%5,%6,%7}, {%8,%9}, {%0,%1,%2,%3};"
        : "+f"(d[0]), "+f"(d[1]), "+f"(d[2]), "+f"(d[3])
        : "r"(a.x), "r"(a.y), "r"(a.z), "r"(a.w), "r"(b.x), "r"(b.y));
}
// packed fp32x2
__device__ __forceinline__ ull pk2(float x, float y) {
    ull r; asm("mov.b64 %0, {%1, %2};" : "=l"(r) : "f"(x), "f"(y)); return r;
}
__device__ __forceinline__ void upk2(ull v, float& x, float& y) {
    asm("mov.b64 {%0, %1}, %2;" : "=f"(x), "=f"(y) : "l"(v));
}
__device__ __forceinline__ ull ffma2(ull a, ull b, ull c) {
    ull d; asm("fma.rn.f32x2 %0, %1, %2, %3;" : "=l"(d) : "l"(a), "l"(b), "l"(c)); return d;
}
__device__ __forceinline__ ull mul2(ull a, ull b) {
    ull d; asm("mul.rn.f32x2 %0, %1, %2;" : "=l"(d) : "l"(a), "l"(b)); return d;
}

// ============================================================
// Fused LayerNorm + A-fragment pack. CTA = 32 tokens.
// ============================================================
__global__ void __launch_bounds__(256) ln_pack_a(
    const float* __restrict__ X, const float* __restrict__ gamma)
{
    __shared__ float smu[32], srs[32];
    const int t0 = blockIdx.x * 32;
    const int w = threadIdx.x >> 5, lane = threadIdx.x & 31;

#pragma unroll
    for (int i = 0; i < 4; i++) {
        int tok = t0 + w * 4 + i;
        const float4* row = (const float4*)(X + (size_t)tok * DIM);
        float4 v0 = row[lane * 2], v1 = row[lane * 2 + 1];
        float s  = (v0.x + v0.y) + (v0.z + v0.w) + (v1.x + v1.y) + (v1.z + v1.w);
        float ss = v0.x * v0.x + v0.y * v0.y + v0.z * v0.z + v0.w * v0.w
                 + v1.x * v1.x + v1.y * v1.y + v1.z * v1.z + v1.w * v1.w;
#pragma unroll
        for (int o = 16; o; o >>= 1) {
            s  += __shfl_xor_sync(0xffffffffu, s, o);
            ss += __shfl_xor_sync(0xffffffffu, ss, o);
        }
        if (lane == 0) {
            float mu = s * (1.f / DIM);
            float var = fmaxf(ss * (1.f / DIM) - mu * mu, 0.f);
            smu[w * 4 + i] = mu;
            srs[w * 4 + i] = rsqrtf(var + 1e-5f);
        }
    }
    __syncthreads();

#pragma unroll
    for (int fi = 0; fi < 4; fi++) {
        const int f = w * 4 + fi;
        const int lm = f >> 4, k16 = f & 15;
        const int rl0 = lm * 16 + (lane >> 2);
        const int rl1 = rl0 + 8;
        const int row0 = t0 + rl0, row1 = t0 + rl1;
        const int kc = (k16 << 4) + ((lane & 3) << 1);

        float2 x00 = *(const float2*)(X + (size_t)row0 * DIM + kc);
        float2 x01 = *(const float2*)(X + (size_t)row0 * DIM + kc + 8);
        float2 x10 = *(const float2*)(X + (size_t)row1 * DIM + kc);
        float2 x11 = *(const float2*)(X + (size_t)row1 * DIM + kc + 8);
        float mu0 = smu[rl0], rs0 = srs[rl0];
        float mu1 = smu[rl1], rs1 = srs[rl1];
        float2 g0 = *(const float2*)(gamma + kc);
        float2 g1 = *(const float2*)(gamma + kc + 8);
        x00.x = (x00.x - mu0) * rs0 * g0.x; x00.y = (x00.y - mu0) * rs0 * g0.y;
        x01.x = (x01.x - mu0) * rs0 * g1.x; x01.y = (x01.y - mu0) * rs0 * g1.y;
        x10.x = (x10.x - mu1) * rs1 * g0.x; x10.y = (x10.y - mu1) * rs1 * g0.y;
        x11.x = (x11.x - mu1) * rs1 * g1.x; x11.y = (x11.y - mu1) * rs1 * g1.y;

        uint4 h, l;
        split2(x00.x, x00.y, h.x, l.x);
        split2(x10.x, x10.y, h.y, l.y);
        split2(x01.x, x01.y, h.z, l.z);
        split2(x11.x, x11.y, h.w, l.w);
        const size_t fragid = (size_t)(t0 / 16 + lm) * 16 + k16;
        g_fah[fragid * 32 + lane] = h;
        g_fal[fragid * 32 + lane] = l;
    }
}

// ============================================================
// Pack B (weights, [K=256][N]) into mma B-fragment layout.
// ============================================================
__global__ void __launch_bounds__(256) pack_b(
    const float* __restrict__ W, uint2* __restrict__ Bh, uint2* __restrict__ Bl, int N)
{
    const int t = blockIdx.x * 256 + threadIdx.x;
    const int lane = t & 31;
    const int k16 = (t >> 5) & 15;
    const int n8 = t >> 9;
    const int k = (k16 << 4) + ((lane & 3) << 1);
    const int n = (n8 << 3) + (lane >> 2);
    float w0 = W[(size_t)k * N + n];
    float w1 = W[(size_t)(k + 1) * N + n];
    float w2 = W[(size_t)(k + 8) * N + n];
    float w3 = W[(size_t)(k + 9) * N + n];
    uint2 h, l;
    split2(w0, w1, h.x, l.x);
    split2(w2, w3, h.y, l.y);
    Bh[t] = h;
    Bl[t] = l;
}

// ============================================================
// Warp-MMA GEMM: CTA 128x128, 4 warps of 64x64, K=256.
// ============================================================
__global__ void __launch_bounds__(128, 2) gemm_mma(
    const uint4* __restrict__ FAh, const uint4* __restrict__ FAl,
    const uint2* __restrict__ FBh, const uint2* __restrict__ FBl,
    float* __restrict__ C, int N)
{
    const int lane = threadIdx.x & 31;
    const int wid = threadIdx.x >> 5;
    const int m16b = blockIdx.y * 8 + (wid & 1) * 4;
    const int n8b  = blockIdx.x * 16 + (wid >> 1) * 8;

    const uint4* pAh = FAh + (size_t)m16b * 16 * 32 + lane;
    const uint4* pAl = FAl + (size_t)m16b * 16 * 32 + lane;
    const uint2* pBh = FBh + (size_t)n8b * 16 * 32 + lane;
    const uint2* pBl = FBl + (size_t)n8b * 16 * 32 + lane;

    float acc[4][8][4];
#pragma unroll
    for (int i = 0; i < 4; i++)
#pragma unroll
        for (int j = 0; j < 8; j++)
#pragma unroll
            for (int r = 0; r < 4; r++) acc[i][j][r] = 0.f;

#pragma unroll 2
    for (int kk = 0; kk < 16; kk++) {
        uint2 bh[8], bl[8];
#pragma unroll
        for (int j = 0; j < 8; j++) {
            bh[j] = pBh[(j * 16 + kk) * 32];
            bl[j] = pBl[(j * 16 + kk) * 32];
        }
#pragma unroll
        for (int i = 0; i < 4; i++) {
            uint4 ah = pAh[(i * 16 + kk) * 32];
            uint4 al = pAl[(i * 16 + kk) * 32];
#pragma unroll
            for (int j = 0; j < 8; j++) {
                mma_bf16(acc[i][j], ah, bh[j]);
                mma_bf16(acc[i][j], ah, bl[j]);
                mma_bf16(acc[i][j], al, bh[j]);
            }
        }
    }

    const int r0 = (m16b << 4) + (lane >> 2);
    const int c0 = (n8b << 3) + ((lane & 3) << 1);
#pragma unroll
    for (int i = 0; i < 4; i++) {
        const size_t rowa = (size_t)(r0 + i * 16) * N;
        const size_t rowb = rowa + 8 * N;
#pragma unroll
        for (int j = 0; j < 8; j++) {
            *(float2*)(C + rowa + c0 + j * 8) = make_float2(acc[i][j][0], acc[i][j][1]);
            *(float2*)(C + rowb + c0 + j * 8) = make_float2(acc[i][j][2], acc[i][j][3]);
        }
    }
}

// ============================================================
// Attention v4: online (flash-style) softmax over key chunks of 16.
// No sim[53] array -> ~95 live regs -> 5 CTAs/SM.
// Output split to bf16 hi/lo, stored directly as A-frag words.
// ============================================================
__global__ void __launch_bounds__(128) attn_kernel(
    const float* __restrict__ mem_kv, const float* __restrict__ bias_table)
{
    __shared__ float ks[2][NKEY][DH];
    __shared__ float vs[2][NKEY][DH];
    __shared__ float bias_s[2][169];

    const int u = threadIdx.x >> 6;
    const int tid = threadIdx.x & 63;
    const int pair = blockIdx.x * 2 + u;
    const int b = pair >> 3;
    const int h = pair & 7;
    const size_t tok0 = (size_t)b * WQ;

    if (tid < 32) {
        int m = tid >> 3, c4 = tid & 7;
        *(float4*)&ks[u][m][c4 * 4] = *((const float4*)(mem_kv + (size_t)(h * NMEM + m) * DH) + c4);
        *(float4*)&vs[u][m][c4 * 4] = *((const float4*)(mem_kv + (size_t)(NHEADS * NMEM * DH)
                                                        + (size_t)(h * NMEM + m) * DH) + c4);
    }
    for (int f = tid; f < WQ * 8; f += 64) {
        int i = f >> 3, c4 = f & 7;
        const float* base = g_qkv + (tok0 + i) * NQKV + h * DH;
        *(float4*)&ks[u][NMEM + i][c4 * 4] = *((const float4*)(base + 256) + c4);
        *(float4*)&vs[u][NMEM + i][c4 * 4] = *((const float4*)(base + 512) + c4);
    }
    for (int f = tid; f < 169; f += 64)
        bias_s[u][f] = bias_table[f * NHEADS + h];
    __syncthreads();

    if (tid < WQ) {
        const int i = tid;
        const size_t tok = tok0 + i;
        const ulonglong2* qp = (const ulonglong2*)(g_qkv + tok * NQKV + h * DH);
        ull q2[16];
#pragma unroll
        for (int c4 = 0; c4 < 8; c4++) {
            ulonglong2 t = qp[c4];
            q2[c4 * 2] = t.x; q2[c4 * 2 + 1] = t.y;
        }
        const int yi = i / 7, xi = i % 7;
        const int bbase = (yi + 6) * 13 + (xi + 6);   // bias idx = bbase - yj*13 - xj
        const float scale = 0.17677669529663687f;

        float m = -1e30f, l = 0.f;
        ull o2[16];
#pragma unroll
        for (int c = 0; c < 16; c++) o2[c] = 0ull;

#pragma unroll
        for (int cc = 0; cc < 4; cc++) {
            const int j0 = cc * 16;
            const int CN = (cc == 3) ? 5 : 16;
            float s[16];
#pragma unroll
            for (int jj = 0; jj < 16; jj++) {
                if (jj >= CN) break;
                const int j = j0 + jj;
                ull s2 = 0ull;
#pragma unroll
                for (int c4 = 0; c4 < 8; c4++) {
                    ulonglong2 t = ((const ulonglong2*)&ks[u][j][0])[c4];
                    s2 = ffma2(q2[c4 * 2], t.x, s2);
                    s2 = ffma2(q2[c4 * 2 + 1], t.y, s2);
                }
                float lo, hi; upk2(s2, lo, hi);
                float sv = (lo + hi) * scale;
                if (j >= NMEM) {
                    const int wk = j - NMEM;
                    const int yj = wk / 7, xj = wk % 7;
                    sv += bias_s[u][bbase - yj * 13 - xj];
                }
                s[jj] = sv;
            }
            float mn = m;
#pragma unroll
            for (int jj = 0; jj < 16; jj++) { if (jj >= CN) break; mn = fmaxf(mn, s[jj]); }
            const float r = __expf(m - mn);
            m = mn;
            l *= r;
            const ull r2 = pk2(r, r);
#pragma unroll
            for (int c = 0; c < 16; c++) o2[c] = mul2(o2[c], r2);
#pragma unroll
            for (int jj = 0; jj < 16; jj++) {
                if (jj >= CN) break;
                const int j = j0 + jj;
                const float p = __expf(s[jj] - m);
                l += p;
                const ull p2 = pk2(p, p);
#pragma unroll
                for (int c4 = 0; c4 < 8; c4++) {
                    ulonglong2 t = ((const ulonglong2*)&vs[u][j][0])[c4];
                    o2[c4 * 2]     = ffma2(p2, t.x, o2[c4 * 2]);
                    o2[c4 * 2 + 1] = ffma2(p2, t.y, o2[c4 * 2 + 1]);
                }
            }
        }
        const float inv = 1.f / l;
        float outv[32];
#pragma unroll
        for (int c = 0; c < 16; c++) {
            float lo, hi; upk2(o2[c], lo, hi);
            outv[2 * c] = lo * inv; outv[2 * c + 1] = hi * inv;
        }
        // --- direct A-fragment word stores ---
        const int r = (int)(tok & 15);
        const size_t m16 = tok >> 4;
        const int ybit = (r < 8) ? 0 : 1;
#pragma unroll
        for (int c16 = 0; c16 < 2; c16++) {
            const size_t fbase = (m16 * 16 + 2 * h + c16) * 32;
#pragma unroll
            for (int lw = 0; lw < 4; lw++) {
                const int lane_t = (r & 7) * 4 + lw;
                uint32_t* wh = (uint32_t*)(g_fah + fbase + lane_t);
                uint32_t* wl = (uint32_t*)(g_fal + fbase + lane_t);
                uint32_t hw0, lw0, hw1, lw1;
                split2(outv[c16 * 16 + lw * 2],     outv[c16 * 16 + lw * 2 + 1], hw0, lw0);
                split2(outv[c16 * 16 + lw * 2 + 8], outv[c16 * 16 + lw * 2 + 9], hw1, lw1);
                wh[ybit]     = hw0;
                wh[ybit + 2] = hw1;
                wl[ybit]     = lw0;
                wl[ybit + 2] = lw1;
            }
        }
    }
}

// ============================================================
extern "C" void kernel_launch(void* const* d_in, const int* in_sizes, int n_in,
                              void* d_out, int out_size) {
    const float* x          = (const float*)d_in[0];
    const float* gamma      = (const float*)d_in[1];
    const float* w_qkv      = (const float*)d_in[2];
    const float* mem_kv     = (const float*)d_in[3];
    const float* bias_table = (const float*)d_in[4];
    const float* w_out      = (const float*)d_in[5];
    float* out = (float*)d_out;

    float* qkv_p;
    cudaGetSymbolAddress((void**)&qkv_p, g_qkv);
    uint4 *fah, *fal;
    cudaGetSymbolAddress((void**)&fah, g_fah);
    cudaGetSymbolAddress((void**)&fal, g_fal);
    uint2 *fbh1, *fbl1, *fbh2, *fbl2;
    cudaGetSymbolAddress((void**)&fbh1, g_fbh1);
    cudaGetSymbolAddress((void**)&fbl1, g_fbl1);
    cudaGetSymbolAddress((void**)&fbh2, g_fbh2);
    cudaGetSymbolAddress((void**)&fbl2, g_fbl2);

    pack_b<<<(NQKV / 8) * 16 * 32 / 256, 256>>>(w_qkv, fbh1, fbl1, NQKV);
    pack_b<<<(DIM / 8) * 16 * 32 / 256, 256>>>(w_out, fbh2, fbl2, DIM);
    ln_pack_a<<<TOKENS / 32, 256>>>(x, gamma);
    gemm_mma<<<dim3(NQKV / 128, TOKENS / 128), 128>>>(fah, fal, fbh1, fbl1, qkv_p, NQKV);
    attn_kernel<<<NWIN * NHEADS / 2, 128>>>(mem_kv, bias_table);
    gemm_mma<<<dim3(DIM / 128, TOKENS / 128), 128>>>(fah, fal, fbh2, fbl2, out, DIM);
}

// round 8
// speedup vs baseline: 2.9330x; 1.0773x over previous
#include <cuda_runtime.h>
#include <cuda_bf16.h>
#include <cstdint>

#define TOKENS 200704          // 16*16*16*49
#define DIM 256
#define NQKV 768
#define NWIN 4096
#define WQ 49
#define NKEY 53
#define NMEM 4
#define DH 32
#define NHEADS 8

#define KPAD 56
#define KSTRIDE 20             // u32 per K smem row (bank-conflict-free)
#define VSTRIDE 36             // u32 per Vt smem row

typedef unsigned long long ull;

// ---- scratch (static device globals; no runtime allocation) ----
__device__ float g_qkv[(size_t)TOKENS * NQKV];        // 616 MB
// fragment-major A: frag(m16,k16) -> 32 lanes x uint4
__device__ uint4 g_fah[(size_t)(TOKENS / 16) * 16 * 32];
__device__ uint4 g_fal[(size_t)(TOKENS / 16) * 16 * 32];
// fragment-major B: frag(n8,k16) -> 32 lanes x uint2
__device__ uint2 g_fbh1[(NQKV / 8) * 16 * 32];
__device__ uint2 g_fbl1[(NQKV / 8) * 16 * 32];
__device__ uint2 g_fbh2[(DIM / 8) * 16 * 32];
__device__ uint2 g_fbl2[(DIM / 8) * 16 * 32];

// ---- helpers ----
__device__ __forceinline__ uint32_t bpack(float x, float y) {
    __nv_bfloat162 t = __floats2bfloat162_rn(x, y);   // low half = x
    return *(uint32_t*)&t;
}
__device__ __forceinline__ void split2(float x, float y, uint32_t& hw, uint32_t& lw) {
    hw = bpack(x, y);
    float hx = __uint_as_float(hw << 16);
    float hy = __uint_as_float(hw & 0xffff0000u);
    lw = bpack(x - hx, y - hy);
}
__device__ __forceinline__ void mma_bf16(float* d, const uint4& a, const uint2& b) {
    asm volatile("mma.sync.aligned.m16n8k16.row.col.f32.bf16.bf16.f32 "
        "{%0,%1,%2,%3}, {%4,%5,%6,%7}, {%8,%9}, {%0,%1,%2,%3};"
        : "+f"(d[0]), "+f"(d[1]), "+f"(d[2]), "+f"(d[3])
        : "r"(a.x), "r"(a.y), "r"(a.z), "r"(a.w), "r"(b.x), "r"(b.y));
}
__device__ __forceinline__ void mma4(float* d,
    uint32_t a0, uint32_t a1, uint32_t a2, uint32_t a3, uint32_t b0, uint32_t b1) {
    asm volatile("mma.sync.aligned.m16n8k16.row.col.f32.bf16.bf16.f32 "
        "{%0,%1,%2,%3}, {%4,%5,%6,%7}, {%8,%9}, {%0,%1,%2,%3};"
        : "+f"(d[0]), "+f"(d[1]), "+f"(d[2]), "+f"(d[3])
        : "r"(a0), "r"(a1), "r"(a2), "r"(a3), "r"(b0), "r"(b1));
}

// ============================================================
// Fused LayerNorm + A-fragment pack. CTA = 32 tokens.
// ============================================================
__global__ void __launch_bounds__(256) ln_pack_a(
    const float* __restrict__ X, const float* __restrict__ gamma)
{
    __shared__ float smu[32], srs[32];
    const int t0 = blockIdx.x * 32;
    const int w = threadIdx.x >> 5, lane = threadIdx.x & 31;

#pragma unroll
    for (int i = 0; i < 4; i++) {
        int tok = t0 + w * 4 + i;
        const float4* row = (const float4*)(X + (size_t)tok * DIM);
        float4 v0 = row[lane * 2], v1 = row[lane * 2 + 1];
        float s  = (v0.x + v0.y) + (v0.z + v0.w) + (v1.x + v1.y) + (v1.z + v1.w);
        float ss = v0.x * v0.x + v0.y * v0.y + v0.z * v0.z + v0.w * v0.w
                 + v1.x * v1.x + v1.y * v1.y + v1.z * v1.z + v1.w * v1.w;
#pragma unroll
        for (int o = 16; o; o >>= 1) {
            s  += __shfl_xor_sync(0xffffffffu, s, o);
            ss += __shfl_xor_sync(0xffffffffu, ss, o);
        }
        if (lane == 0) {
            float mu = s * (1.f / DIM);
            float var = fmaxf(ss * (1.f / DIM) - mu * mu, 0.f);
            smu[w * 4 + i] = mu;
            srs[w * 4 + i] = rsqrtf(var + 1e-5f);
        }
    }
    __syncthreads();

#pragma unroll
    for (int fi = 0; fi < 4; fi++) {
        const int f = w * 4 + fi;
        const int lm = f >> 4, k16 = f & 15;
        const int rl0 = lm * 16 + (lane >> 2);
        const int rl1 = rl0 + 8;
        const int row0 = t0 + rl0, row1 = t0 + rl1;
        const int kc = (k16 << 4) + ((lane & 3) << 1);

        float2 x00 = *(const float2*)(X + (size_t)row0 * DIM + kc);
        float2 x01 = *(const float2*)(X + (size_t)row0 * DIM + kc + 8);
        float2 x10 = *(const float2*)(X + (size_t)row1 * DIM + kc);
        float2 x11 = *(const float2*)(X + (size_t)row1 * DIM + kc + 8);
        float mu0 = smu[rl0], rs0 = srs[rl0];
        float mu1 = smu[rl1], rs1 = srs[rl1];
        float2 g0 = *(const float2*)(gamma + kc);
        float2 g1 = *(const float2*)(gamma + kc + 8);
        x00.x = (x00.x - mu0) * rs0 * g0.x; x00.y = (x00.y - mu0) * rs0 * g0.y;
        x01.x = (x01.x - mu0) * rs0 * g1.x; x01.y = (x01.y - mu0) * rs0 * g1.y;
        x10.x = (x10.x - mu1) * rs1 * g0.x; x10.y = (x10.y - mu1) * rs1 * g0.y;
        x11.x = (x11.x - mu1) * rs1 * g1.x; x11.y = (x11.y - mu1) * rs1 * g1.y;

        uint4 h, l;
        split2(x00.x, x00.y, h.x, l.x);
        split2(x10.x, x10.y, h.y, l.y);
        split2(x01.x, x01.y, h.z, l.z);
        split2(x11.x, x11.y, h.w, l.w);
        const size_t fragid = (size_t)(t0 / 16 + lm) * 16 + k16;
        g_fah[fragid * 32 + lane] = h;
        g_fal[fragid * 32 + lane] = l;
    }
}

// ============================================================
// Pack B (weights, [K=256][N]) into mma B-fragment layout.
// ============================================================
__global__ void __launch_bounds__(256) pack_b(
    const float* __restrict__ W, uint2* __restrict__ Bh, uint2* __restrict__ Bl, int N)
{
    const int t = blockIdx.x * 256 + threadIdx.x;
    const int lane = t & 31;
    const int k16 = (t >> 5) & 15;
    const int n8 = t >> 9;
    const int k = (k16 << 4) + ((lane & 3) << 1);
    const int n = (n8 << 3) + (lane >> 2);
    float w0 = W[(size_t)k * N + n];
    float w1 = W[(size_t)(k + 1) * N + n];
    float w2 = W[(size_t)(k + 8) * N + n];
    float w3 = W[(size_t)(k + 9) * N + n];
    uint2 h, l;
    split2(w0, w1, h.x, l.x);
    split2(w2, w3, h.y, l.y);
    Bh[t] = h;
    Bl[t] = l;
}

// ============================================================
// Warp-MMA GEMM: CTA 128x128, 4 warps of 64x64, K=256.
// ============================================================
__global__ void __launch_bounds__(128, 2) gemm_mma(
    const uint4* __restrict__ FAh, const uint4* __restrict__ FAl,
    const uint2* __restrict__ FBh, const uint2* __restrict__ FBl,
    float* __restrict__ C, int N)
{
    const int lane = threadIdx.x & 31;
    const int wid = threadIdx.x >> 5;
    const int m16b = blockIdx.y * 8 + (wid & 1) * 4;
    const int n8b  = blockIdx.x * 16 + (wid >> 1) * 8;

    const uint4* pAh = FAh + (size_t)m16b * 16 * 32 + lane;
    const uint4* pAl = FAl + (size_t)m16b * 16 * 32 + lane;
    const uint2* pBh = FBh + (size_t)n8b * 16 * 32 + lane;
    const uint2* pBl = FBl + (size_t)n8b * 16 * 32 + lane;

    float acc[4][8][4];
#pragma unroll
    for (int i = 0; i < 4; i++)
#pragma unroll
        for (int j = 0; j < 8; j++)
#pragma unroll
            for (int r = 0; r < 4; r++) acc[i][j][r] = 0.f;

#pragma unroll 2
    for (int kk = 0; kk < 16; kk++) {
        uint2 bh[8], bl[8];
#pragma unroll
        for (int j = 0; j < 8; j++) {
            bh[j] = pBh[(j * 16 + kk) * 32];
            bl[j] = pBl[(j * 16 + kk) * 32];
        }
#pragma unroll
        for (int i = 0; i < 4; i++) {
            uint4 ah = pAh[(i * 16 + kk) * 32];
            uint4 al = pAl[(i * 16 + kk) * 32];
#pragma unroll
            for (int j = 0; j < 8; j++) {
                mma_bf16(acc[i][j], ah, bh[j]);
                mma_bf16(acc[i][j], ah, bl[j]);
                mma_bf16(acc[i][j], al, bh[j]);
            }
        }
    }

    const int r0 = (m16b << 4) + (lane >> 2);
    const int c0 = (n8b << 3) + ((lane & 3) << 1);
#pragma unroll
    for (int i = 0; i < 4; i++) {
        const size_t rowa = (size_t)(r0 + i * 16) * N;
        const size_t rowb = rowa + 8 * N;
#pragma unroll
        for (int j = 0; j < 8; j++) {
            *(float2*)(C + rowa + c0 + j * 8) = make_float2(acc[i][j][0], acc[i][j][1]);
            *(float2*)(C + rowb + c0 + j * 8) = make_float2(acc[i][j][2], acc[i][j][3]);
        }
    }
}

// ============================================================
// Attention v5: tensor-core. CTA = (window, head), 4 warps = 4 m16 blocks.
// S = QK^T (3-product bf16 split, fp32 acc) -> bias/mask -> softmax (fp32)
// -> P packed to A-frags in-register -> O = PV (3-product) -> direct
// A-frag word stores for the out GEMM.
// ============================================================
__global__ void __launch_bounds__(128, 4) attn_kernel(
    const float* __restrict__ mem_kv, const float* __restrict__ bias_table)
{
    __shared__ uint32_t KsmH[KPAD * KSTRIDE];
    __shared__ uint32_t KsmL[KPAD * KSTRIDE];
    __shared__ uint32_t VtH[32 * VSTRIDE];
    __shared__ uint32_t VtL[32 * VSTRIDE];
    __shared__ float bias_s[169];
    __shared__ int tab_s[56];

    const int cta = blockIdx.x;
    const int b = cta >> 3, h = cta & 7;
    const int tid = threadIdx.x, wid = tid >> 5, lane = tid & 31;
    const size_t tok0 = (size_t)b * WQ;
    const float scale = 0.17677669529663687f;   // 1/sqrt(32)

    // ---- stage K: 56 keys x 16 bf16-pair words (hi/lo) ----
    for (int idx = tid; idx < KPAD * 16; idx += 128) {
        int n = idx >> 4, p = idx & 15;
        float2 kv = make_float2(0.f, 0.f);
        if (n < NMEM)
            kv = *(const float2*)(mem_kv + ((h * NMEM + n) << 5) + 2 * p);
        else if (n < NKEY)
            kv = *(const float2*)(g_qkv + (tok0 + n - NMEM) * NQKV + 256 + h * 32 + 2 * p);
        uint32_t hw, lw; split2(kv.x, kv.y, hw, lw);
        KsmH[n * KSTRIDE + p] = hw;
        KsmL[n * KSTRIDE + p] = lw;
    }
    // ---- stage V transposed: Vt[dh n][key-pair p] ----
    for (int idx = tid; idx < 32 * 32; idx += 128) {
        int p = idx >> 5, n = idx & 31;
        int k0 = 2 * p, k1 = 2 * p + 1;
        float v0 = 0.f, v1 = 0.f;
        if (k0 < NMEM)       v0 = mem_kv[1024 + ((h * NMEM + k0) << 5) + n];
        else if (k0 < NKEY)  v0 = g_qkv[(tok0 + k0 - NMEM) * NQKV + 512 + h * 32 + n];
        if (k1 < NMEM)       v1 = mem_kv[1024 + ((h * NMEM + k1) << 5) + n];
        else if (k1 < NKEY)  v1 = g_qkv[(tok0 + k1 - NMEM) * NQKV + 512 + h * 32 + n];
        uint32_t hw, lw; split2(v0, v1, hw, lw);
        VtH[n * VSTRIDE + p] = hw;
        VtL[n * VSTRIDE + p] = lw;
    }
    for (int f = tid; f < 169; f += 128) bias_s[f] = bias_table[f * NHEADS + h];
    if (tid < WQ) { int yj = tid / 7, xj = tid % 7; tab_s[tid + NMEM] = yj * 13 + xj; }
    __syncthreads();

    // ---- Q A-frags (rows clamped to 48 for pads), scale folded ----
    const int qr = lane >> 2;          // 0..7
    const int qc = (lane & 3) * 2;     // 0,2,4,6
    const int ra = wid * 16 + qr, rb = ra + 8;
    const int raC = min(ra, WQ - 1), rbC = min(rb, WQ - 1);
    uint32_t qh[2][4], ql[2][4];
#pragma unroll
    for (int k16 = 0; k16 < 2; k16++) {
        const float* bA = g_qkv + (tok0 + raC) * NQKV + h * 32 + k16 * 16;
        const float* bB = g_qkv + (tok0 + rbC) * NQKV + h * 32 + k16 * 16;
        float2 x0 = *(const float2*)(bA + qc);
        float2 x1 = *(const float2*)(bB + qc);
        float2 x2 = *(const float2*)(bA + qc + 8);
        float2 x3 = *(const float2*)(bB + qc + 8);
        split2(x0.x * scale, x0.y * scale, qh[k16][0], ql[k16][0]);
        split2(x1.x * scale, x1.y * scale, qh[k16][1], ql[k16][1]);
        split2(x2.x * scale, x2.y * scale, qh[k16][2], ql[k16][2]);
        split2(x3.x * scale, x3.y * scale, qh[k16][3], ql[k16][3]);
    }

    // ---- S = Q K^T ----
    float S[7][4];
#pragma unroll
    for (int n8 = 0; n8 < 7; n8++)
#pragma unroll
        for (int r = 0; r < 4; r++) S[n8][r] = 0.f;

    const int kn = lane >> 2;
#pragma unroll
    for (int n8 = 0; n8 < 7; n8++) {
        const int key = n8 * 8 + kn;
#pragma unroll
        for (int k16 = 0; k16 < 2; k16++) {
            const int a = key * KSTRIDE + (lane & 3) + 8 * k16;
            uint32_t bh0 = KsmH[a], bh1 = KsmH[a + 4];
            uint32_t bl0 = KsmL[a], bl1 = KsmL[a + 4];
            mma4(S[n8], qh[k16][0], qh[k16][1], qh[k16][2], qh[k16][3], bh0, bh1);
            mma4(S[n8], qh[k16][0], qh[k16][1], qh[k16][2], qh[k16][3], bl0, bl1);
            mma4(S[n8], ql[k16][0], ql[k16][1], ql[k16][2], ql[k16][3], bh0, bh1);
        }
    }

    // ---- bias + mask ----
    const int base_ra = (raC / 7 + 6) * 13 + raC % 7 + 6;
    const int base_rb = (rbC / 7 + 6) * 13 + rbC % 7 + 6;
#pragma unroll
    for (int n8 = 0; n8 < 7; n8++) {
#pragma unroll
        for (int e = 0; e < 2; e++) {
            int col = n8 * 8 + qc + e;
            if (col >= NKEY) {
                S[n8][e] = -1e30f; S[n8][2 + e] = -1e30f;
            } else if (col >= NMEM) {
                int t = tab_s[col];
                S[n8][e]     += bias_s[base_ra - t];
                S[n8][2 + e] += bias_s[base_rb - t];
            }
        }
    }

    // ---- softmax (rows ra, rb), fp32 exact ----
    float mA = -1e30f, mB = -1e30f;
#pragma unroll
    for (int n8 = 0; n8 < 7; n8++) {
        mA = fmaxf(mA, fmaxf(S[n8][0], S[n8][1]));
        mB = fmaxf(mB, fmaxf(S[n8][2], S[n8][3]));
    }
    mA = fmaxf(mA, __shfl_xor_sync(0xffffffffu, mA, 1));
    mA = fmaxf(mA, __shfl_xor_sync(0xffffffffu, mA, 2));
    mB = fmaxf(mB, __shfl_xor_sync(0xffffffffu, mB, 1));
    mB = fmaxf(mB, __shfl_xor_sync(0xffffffffu, mB, 2));
    float lA = 0.f, lB = 0.f;
#pragma unroll
    for (int n8 = 0; n8 < 7; n8++) {
        S[n8][0] = __expf(S[n8][0] - mA); lA += S[n8][0];
        S[n8][1] = __expf(S[n8][1] - mA); lA += S[n8][1];
        S[n8][2] = __expf(S[n8][2] - mB); lB += S[n8][2];
        S[n8][3] = __expf(S[n8][3] - mB); lB += S[n8][3];
    }
    lA += __shfl_xor_sync(0xffffffffu, lA, 1);
    lA += __shfl_xor_sync(0xffffffffu, lA, 2);
    lB += __shfl_xor_sync(0xffffffffu, lB, 1);
    lB += __shfl_xor_sync(0xffffffffu, lB, 2);
    const float invA = 1.f / lA, invB = 1.f / lB;
#pragma unroll
    for (int n8 = 0; n8 < 7; n8++) {
        S[n8][0] *= invA; S[n8][1] *= invA;
        S[n8][2] *= invB; S[n8][3] *= invB;
    }

    // ---- pack P into A-frags (hi/lo) ----
    uint32_t ph[4][4], pl[4][4];
#pragma unroll
    for (int k16 = 0; k16 < 4; k16++) {
        const int na = 2 * k16, nb = na + 1;
        split2(S[na][0], S[na][1], ph[k16][0], pl[k16][0]);
        split2(S[na][2], S[na][3], ph[k16][1], pl[k16][1]);
        if (nb < 7) {
            split2(S[nb][0], S[nb][1], ph[k16][2], pl[k16][2]);
            split2(S[nb][2], S[nb][3], ph[k16][3], pl[k16][3]);
        } else {
            ph[k16][2] = ph[k16][3] = 0; pl[k16][2] = pl[k16][3] = 0;
        }
    }

    // ---- O = P V ----
    float O[4][4];
#pragma unroll
    for (int nv = 0; nv < 4; nv++)
#pragma unroll
        for (int r = 0; r < 4; r++) O[nv][r] = 0.f;
#pragma unroll
    for (int k16 = 0; k16 < 4; k16++) {
#pragma unroll
        for (int nv = 0; nv < 4; nv++) {
            const int a = (nv * 8 + kn) * VSTRIDE + (lane & 3) + 8 * k16;
            uint32_t vh0 = VtH[a], vh1 = VtH[a + 4];
            uint32_t vl0 = VtL[a], vl1 = VtL[a + 4];
            mma4(O[nv], ph[k16][0], ph[k16][1], ph[k16][2], ph[k16][3], vh0, vh1);
            mma4(O[nv], ph[k16][0], ph[k16][1], ph[k16][2], ph[k16][3], vl0, vl1);
            mma4(O[nv], pl[k16][0], pl[k16][1], pl[k16][2], pl[k16][3], vh0, vh1);
        }
    }

    // ---- epilogue: direct A-frag word stores for out GEMM ----
#pragma unroll
    for (int half = 0; half < 2; half++) {
        const int row = half ? rb : ra;
        if (row < WQ) {
            const size_t tok = tok0 + row;
            const size_t m16g = tok >> 4;
            const int rr = (int)(tok & 15);
            const int comp_base = (rr < 8) ? 0 : 1;
            const int lane_t = 4 * (rr & 7) + (lane & 3);
#pragma unroll
            for (int nv = 0; nv < 4; nv++) {
                const int col = nv * 8 + qc;
                const int c16 = nv >> 1;
                const size_t fragid = m16g * 16 + 2 * h + c16;
                const int comp = comp_base + ((col & 8) ? 2 : 0);
                uint32_t hw, lw;
                split2(O[nv][half * 2], O[nv][half * 2 + 1], hw, lw);
                ((uint32_t*)(g_fah + fragid * 32 + lane_t))[comp] = hw;
                ((uint32_t*)(g_fal + fragid * 32 + lane_t))[comp] = lw;
            }
        }
    }
}

// ============================================================
extern "C" void kernel_launch(void* const* d_in, const int* in_sizes, int n_in,
                              void* d_out, int out_size) {
    const float* x          = (const float*)d_in[0];
    const float* gamma      = (const float*)d_in[1];
    const float* w_qkv      = (const float*)d_in[2];
    const float* mem_kv     = (const float*)d_in[3];
    const float* bias_table = (const float*)d_in[4];
    const float* w_out      = (const float*)d_in[5];
    float* out = (float*)d_out;

    float* qkv_p;
    cudaGetSymbolAddress((void**)&qkv_p, g_qkv);
    uint4 *fah, *fal;
    cudaGetSymbolAddress((void**)&fah, g_fah);
    cudaGetSymbolAddress((void**)&fal, g_fal);
    uint2 *fbh1, *fbl1, *fbh2, *fbl2;
    cudaGetSymbolAddress((void**)&fbh1, g_fbh1);
    cudaGetSymbolAddress((void**)&fbl1, g_fbl1);
    cudaGetSymbolAddress((void**)&fbh2, g_fbh2);
    cudaGetSymbolAddress((void**)&fbl2, g_fbl2);

    pack_b<<<(NQKV / 8) * 16 * 32 / 256, 256>>>(w_qkv, fbh1, fbl1, NQKV);
    pack_b<<<(DIM / 8) * 16 * 32 / 256, 256>>>(w_out, fbh2, fbl2, DIM);
    ln_pack_a<<<TOKENS / 32, 256>>>(x, gamma);
    gemm_mma<<<dim3(NQKV / 128, TOKENS / 128), 128>>>(fah, fal, fbh1, fbl1, qkv_p, NQKV);
    attn_kernel<<<NWIN * NHEADS, 128>>>(mem_kv, bias_table);
    gemm_mma<<<dim3(DIM / 128, TOKENS / 128), 128>>>(fah, fal, fbh2, fbl2, out, DIM);
}

// round 9
// speedup vs baseline: 3.2506x; 1.1083x over previous
#include <cuda_runtime.h>
#include <cuda_bf16.h>
#include <cstdint>

#define TOKENS 200704          // 16*16*16*49
#define DIM 256
#define NQKV 768
#define NWIN 4096
#define WQ 49
#define NKEY 53
#define NMEM 4
#define DH 32
#define NHEADS 8

typedef unsigned long long ull;

// ---- scratch (static device globals; no runtime allocation) ----
// qkv as pre-split bf16 pair-words: word w of row = cols (2w, 2w+1).
// q = words 0..127, k = 128..255, v = 256..383
__device__ uint32_t g_sh[(size_t)TOKENS * 384];   // hi words, 308 MB
__device__ uint32_t g_sl[(size_t)TOKENS * 384];   // lo words
// fragment-major A: frag(m16,k16) -> 32 lanes x uint4
__device__ uint4 g_fah[(size_t)(TOKENS / 16) * 16 * 32];
__device__ uint4 g_fal[(size_t)(TOKENS / 16) * 16 * 32];
// fragment-major B: frag(n8,k16) -> 32 lanes x uint2
__device__ uint2 g_fbh1[(NQKV / 8) * 16 * 32];
__device__ uint2 g_fbl1[(NQKV / 8) * 16 * 32];
__device__ uint2 g_fbh2[(DIM / 8) * 16 * 32];
__device__ uint2 g_fbl2[(DIM / 8) * 16 * 32];
// pre-split memory kv: [h][key 0..3][dh-pair 0..15]
__device__ uint32_t g_mkH[512], g_mkL[512], g_mvH[512], g_mvL[512];

// ---- helpers ----
__device__ __forceinline__ uint32_t bpack(float x, float y) {
    __nv_bfloat162 t = __floats2bfloat162_rn(x, y);   // low half = x
    return *(uint32_t*)&t;
}
__device__ __forceinline__ void split2(float x, float y, uint32_t& hw, uint32_t& lw) {
    hw = bpack(x, y);
    float hx = __uint_as_float(hw << 16);
    float hy = __uint_as_float(hw & 0xffff0000u);
    lw = bpack(x - hx, y - hy);
}
__device__ __forceinline__ uint32_t prmt(uint32_t a, uint32_t b, uint32_t sel) {
    uint32_t d;
    asm("prmt.b32 %0, %1, %2, %3;" : "=r"(d) : "r"(a), "r"(b), "r"(sel));
    return d;
}
__device__ __forceinline__ void mma_bf16(float* d, const uint4& a, const uint2& b) {
    asm volatile("mma.sync.aligned.m16n8k16.row.col.f32.bf16.bf16.f32 "
        "{%0,%1,%2,%3}, {%4,%5,%6,%7}, {%8,%9}, {%0,%1,%2,%3};"
        : "+f"(d[0]), "+f"(d[1]), "+f"(d[2]), "+f"(d[3])
        : "r"(a.x), "r"(a.y), "r"(a.z), "r"(a.w), "r"(b.x), "r"(b.y));
}
__device__ __forceinline__ void mma4(float* d,
    uint32_t a0, uint32_t a1, uint32_t a2, uint32_t a3, uint32_t b0, uint32_t b1) {
    asm volatile("mma.sync.aligned.m16n8k16.row.col.f32.bf16.bf16.f32 "
        "{%0,%1,%2,%3}, {%4,%5,%6,%7}, {%8,%9}, {%0,%1,%2,%3};"
        : "+f"(d[0]), "+f"(d[1]), "+f"(d[2]), "+f"(d[3])
        : "r"(a0), "r"(a1), "r"(a2), "r"(a3), "r"(b0), "r"(b1));
}

// ============================================================
// Pre-split memory kv. One block.
// ============================================================
__global__ void mem_split(const float* __restrict__ mem_kv) {
    int t = threadIdx.x;                 // 0..1023 = [kv][h][key][p]
    int p = t & 15, key = (t >> 4) & 3, h = (t >> 6) & 7, kv = t >> 9;
    float2 v = *(const float2*)(mem_kv + (size_t)(((kv * 8 + h) * 4 + key) * 32) + 2 * p);
    uint32_t hw, lw; split2(v.x, v.y, hw, lw);
    if (kv == 0) { g_mkH[(h * 4 + key) * 16 + p] = hw; g_mkL[(h * 4 + key) * 16 + p] = lw; }
    else         { g_mvH[(h * 4 + key) * 16 + p] = hw; g_mvL[(h * 4 + key) * 16 + p] = lw; }
}

// ============================================================
// Fused LayerNorm + A-fragment pack. CTA = 32 tokens.
// ============================================================
__global__ void __launch_bounds__(256) ln_pack_a(
    const float* __restrict__ X, const float* __restrict__ gamma)
{
    __shared__ float smu[32], srs[32];
    const int t0 = blockIdx.x * 32;
    const int w = threadIdx.x >> 5, lane = threadIdx.x & 31;

#pragma unroll
    for (int i = 0; i < 4; i++) {
        int tok = t0 + w * 4 + i;
        const float4* row = (const float4*)(X + (size_t)tok * DIM);
        float4 v0 = row[lane * 2], v1 = row[lane * 2 + 1];
        float s  = (v0.x + v0.y) + (v0.z + v0.w) + (v1.x + v1.y) + (v1.z + v1.w);
        float ss = v0.x * v0.x + v0.y * v0.y + v0.z * v0.z + v0.w * v0.w
                 + v1.x * v1.x + v1.y * v1.y + v1.z * v1.z + v1.w * v1.w;
#pragma unroll
        for (int o = 16; o; o >>= 1) {
            s  += __shfl_xor_sync(0xffffffffu, s, o);
            ss += __shfl_xor_sync(0xffffffffu, ss, o);
        }
        if (lane == 0) {
            float mu = s * (1.f / DIM);
            float var = fmaxf(ss * (1.f / DIM) - mu * mu, 0.f);
            smu[w * 4 + i] = mu;
            srs[w * 4 + i] = rsqrtf(var + 1e-5f);
        }
    }
    __syncthreads();

#pragma unroll
    for (int fi = 0; fi < 4; fi++) {
        const int f = w * 4 + fi;
        const int lm = f >> 4, k16 = f & 15;
        const int rl0 = lm * 16 + (lane >> 2);
        const int rl1 = rl0 + 8;
        const int row0 = t0 + rl0, row1 = t0 + rl1;
        const int kc = (k16 << 4) + ((lane & 3) << 1);

        float2 x00 = *(const float2*)(X + (size_t)row0 * DIM + kc);
        float2 x01 = *(const float2*)(X + (size_t)row0 * DIM + kc + 8);
        float2 x10 = *(const float2*)(X + (size_t)row1 * DIM + kc);
        float2 x11 = *(const float2*)(X + (size_t)row1 * DIM + kc + 8);
        float mu0 = smu[rl0], rs0 = srs[rl0];
        float mu1 = smu[rl1], rs1 = srs[rl1];
        float2 g0 = *(const float2*)(gamma + kc);
        float2 g1 = *(const float2*)(gamma + kc + 8);
        x00.x = (x00.x - mu0) * rs0 * g0.x; x00.y = (x00.y - mu0) * rs0 * g0.y;
        x01.x = (x01.x - mu0) * rs0 * g1.x; x01.y = (x01.y - mu0) * rs0 * g1.y;
        x10.x = (x10.x - mu1) * rs1 * g0.x; x10.y = (x10.y - mu1) * rs1 * g0.y;
        x11.x = (x11.x - mu1) * rs1 * g1.x; x11.y = (x11.y - mu1) * rs1 * g1.y;

        uint4 h, l;
        split2(x00.x, x00.y, h.x, l.x);
        split2(x10.x, x10.y, h.y, l.y);
        split2(x01.x, x01.y, h.z, l.z);
        split2(x11.x, x11.y, h.w, l.w);
        const size_t fragid = (size_t)(t0 / 16 + lm) * 16 + k16;
        g_fah[fragid * 32 + lane] = h;
        g_fal[fragid * 32 + lane] = l;
    }
}

// ============================================================
// Pack B (weights, [K=256][N]) into mma B-fragment layout.
// ============================================================
__global__ void __launch_bounds__(256) pack_b(
    const float* __restrict__ W, uint2* __restrict__ Bh, uint2* __restrict__ Bl, int N)
{
    const int t = blockIdx.x * 256 + threadIdx.x;
    const int lane = t & 31;
    const int k16 = (t >> 5) & 15;
    const int n8 = t >> 9;
    const int k = (k16 << 4) + ((lane & 3) << 1);
    const int n = (n8 << 3) + (lane >> 2);
    float w0 = W[(size_t)k * N + n];
    float w1 = W[(size_t)(k + 1) * N + n];
    float w2 = W[(size_t)(k + 8) * N + n];
    float w3 = W[(size_t)(k + 9) * N + n];
    uint2 h, l;
    split2(w0, w1, h.x, l.x);
    split2(w2, w3, h.y, l.y);
    Bh[t] = h;
    Bl[t] = l;
}

// ============================================================
// Warp-MMA GEMM: CTA 128x128, 4 warps of 64x64, K=256.
// MODE 0: fp32 C store. MODE 1: split bf16 pair-word store to g_sh/g_sl.
// ============================================================
template<int MODE>
__global__ void __launch_bounds__(128, 2) gemm_mma(
    const uint4* __restrict__ FAh, const uint4* __restrict__ FAl,
    const uint2* __restrict__ FBh, const uint2* __restrict__ FBl,
    float* __restrict__ C, int N)
{
    const int lane = threadIdx.x & 31;
    const int wid = threadIdx.x >> 5;
    const int m16b = blockIdx.y * 8 + (wid & 1) * 4;
    const int n8b  = blockIdx.x * 16 + (wid >> 1) * 8;

    const uint4* pAh = FAh + (size_t)m16b * 16 * 32 + lane;
    const uint4* pAl = FAl + (size_t)m16b * 16 * 32 + lane;
    const uint2* pBh = FBh + (size_t)n8b * 16 * 32 + lane;
    const uint2* pBl = FBl + (size_t)n8b * 16 * 32 + lane;

    float acc[4][8][4];
#pragma unroll
    for (int i = 0; i < 4; i++)
#pragma unroll
        for (int j = 0; j < 8; j++)
#pragma unroll
            for (int r = 0; r < 4; r++) acc[i][j][r] = 0.f;

#pragma unroll 2
    for (int kk = 0; kk < 16; kk++) {
        uint2 bh[8], bl[8];
#pragma unroll
        for (int j = 0; j < 8; j++) {
            bh[j] = pBh[(j * 16 + kk) * 32];
            bl[j] = pBl[(j * 16 + kk) * 32];
        }
#pragma unroll
        for (int i = 0; i < 4; i++) {
            uint4 ah = pAh[(i * 16 + kk) * 32];
            uint4 al = pAl[(i * 16 + kk) * 32];
#pragma unroll
            for (int j = 0; j < 8; j++) {
                mma_bf16(acc[i][j], ah, bh[j]);
                mma_bf16(acc[i][j], ah, bl[j]);
                mma_bf16(acc[i][j], al, bh[j]);
            }
        }
    }

    const int r0 = (m16b << 4) + (lane >> 2);
    const int c0 = (n8b << 3) + ((lane & 3) << 1);
    if (MODE == 0) {
#pragma unroll
        for (int i = 0; i < 4; i++) {
            const size_t rowa = (size_t)(r0 + i * 16) * N;
            const size_t rowb = rowa + 8 * N;
#pragma unroll
            for (int j = 0; j < 8; j++) {
                *(float2*)(C + rowa + c0 + j * 8) = make_float2(acc[i][j][0], acc[i][j][1]);
                *(float2*)(C + rowb + c0 + j * 8) = make_float2(acc[i][j][2], acc[i][j][3]);
            }
        }
    } else {
        const int wbase = n8b * 4 + (lane & 3);
#pragma unroll
        for (int i = 0; i < 4; i++) {
            const size_t ra = (size_t)(r0 + i * 16) * 384;
            const size_t rb = ra + 8 * 384;
#pragma unroll
            for (int j = 0; j < 8; j++) {
                const int w = wbase + j * 4;
                uint32_t hw, lw;
                split2(acc[i][j][0], acc[i][j][1], hw, lw);
                g_sh[ra + w] = hw; g_sl[ra + w] = lw;
                split2(acc[i][j][2], acc[i][j][3], hw, lw);
                g_sh[rb + w] = hw; g_sl[rb + w] = lw;
            }
        }
    }
}

// ============================================================
// Attention v6: tensor-core, pre-split inputs, LDS.64 frag loads.
// K smem: [k16 0..1][key 0..55][w 0..7], word w=2q+b <-> dh-pair p=8*k16+q+4b
// Vt smem: [k16 0..3][dh 0..31][w 0..7], word covers key pair p=8*k16+q+4b
// ============================================================
__global__ void __launch_bounds__(128, 4) attn_kernel(
    const float* __restrict__ bias_table)
{
    __shared__ uint32_t KsmH[2 * 56 * 8];
    __shared__ uint32_t KsmL[2 * 56 * 8];
    __shared__ uint32_t VtH[4 * 32 * 8];
    __shared__ uint32_t VtL[4 * 32 * 8];
    __shared__ float bias_s[169];
    __shared__ int tab_s[56];

    const int cta = blockIdx.x;
    const int b = cta >> 3, h = cta & 7;
    const int tid = threadIdx.x, wid = tid >> 5, lane = tid & 31;
    const size_t tok0 = (size_t)b * WQ;
    const float scale = 0.17677669529663687f;   // 1/sqrt(32)

    // ---- stage K (plain word copies) ----
#pragma unroll
    for (int it = 0; it < 7; it++) {
        const int i = tid + it * 128;            // [k16][key][w]
        const int w = i & 7, key = (i >> 3) % 56, k16 = i / 448;
        const int p = k16 * 8 + (w >> 1) + ((w & 1) << 2);
        uint32_t hw = 0, lw = 0;
        if (key < NMEM) {
            hw = g_mkH[(h * 4 + key) * 16 + p];
            lw = g_mkL[(h * 4 + key) * 16 + p];
        } else if (key < NKEY) {
            const size_t off = (tok0 + key - NMEM) * 384 + 128 + h * 16 + p;
            hw = g_sh[off]; lw = g_sl[off];
        }
        KsmH[i] = hw; KsmL[i] = lw;
    }
    // ---- stage Vt (prmt recombine of token pair words) ----
#pragma unroll
    for (int it = 0; it < 4; it++) {
        const int g = tid + it * 128;            // [k16][m][w], m = dh pair
        const int w = g & 7, m = (g >> 3) & 15, k16 = g >> 7;
        const int p = k16 * 8 + (w >> 1) + ((w & 1) << 2);   // key pair
        uint32_t aH = 0, aL = 0, bH = 0, bL = 0;
        if (p < 2) {
            aH = g_mvH[(h * 4 + 2 * p) * 16 + m];
            aL = g_mvL[(h * 4 + 2 * p) * 16 + m];
            bH = g_mvH[(h * 4 + 2 * p + 1) * 16 + m];
            bL = g_mvL[(h * 4 + 2 * p + 1) * 16 + m];
        } else {
            const int t0 = 2 * p - NMEM;
            if (t0 < WQ) {
                const size_t off = (tok0 + t0) * 384 + 256 + h * 16 + m;
                aH = g_sh[off]; aL = g_sl[off];
            }
            if (t0 + 1 < WQ) {
                const size_t off = (tok0 + t0 + 1) * 384 + 256 + h * 16 + m;
                bH = g_sh[off]; bL = g_sl[off];
            }
        }
        const int de = (k16 * 32 + 2 * m) * 8 + w;
        const int do_ = de + 8;
        VtH[de]  = prmt(aH, bH, 0x5410);
        VtH[do_] = prmt(aH, bH, 0x7632);
        VtL[de]  = prmt(aL, bL, 0x5410);
        VtL[do_] = prmt(aL, bL, 0x7632);
    }
    for (int f = tid; f < 169; f += 128) bias_s[f] = bias_table[f * NHEADS + h];
    if (tid < WQ) { int yj = tid / 7, xj = tid % 7; tab_s[tid + NMEM] = yj * 13 + xj; }
    __syncthreads();

    // ---- Q A-frags (rows clamped for pads) ----
    const int qr = lane >> 2;
    const int qc = (lane & 3) * 2;
    const int ra = wid * 16 + qr, rb = ra + 8;
    const int raC = min(ra, WQ - 1), rbC = min(rb, WQ - 1);
    uint32_t qh[2][4], ql[2][4];
#pragma unroll
    for (int k16 = 0; k16 < 2; k16++) {
        const size_t rA = (tok0 + raC) * 384, rB = (tok0 + rbC) * 384;
        const int wq = h * 16 + k16 * 8 + (lane & 3);
        qh[k16][0] = g_sh[rA + wq];     ql[k16][0] = g_sl[rA + wq];
        qh[k16][1] = g_sh[rB + wq];     ql[k16][1] = g_sl[rB + wq];
        qh[k16][2] = g_sh[rA + wq + 4]; ql[k16][2] = g_sl[rA + wq + 4];
        qh[k16][3] = g_sh[rB + wq + 4]; ql[k16][3] = g_sl[rB + wq + 4];
    }

    // ---- S = Q K^T ----
    float S[7][4];
#pragma unroll
    for (int n8 = 0; n8 < 7; n8++)
#pragma unroll
        for (int r = 0; r < 4; r++) S[n8][r] = 0.f;

    const int kn = lane >> 2;
    const int q2w = (lane & 3) * 2;
#pragma unroll
    for (int n8 = 0; n8 < 7; n8++) {
        const int key = n8 * 8 + kn;
#pragma unroll
        for (int k16 = 0; k16 < 2; k16++) {
            const int a = (k16 * 56 + key) * 8 + q2w;
            const uint2 bh = *(const uint2*)&KsmH[a];
            const uint2 bl = *(const uint2*)&KsmL[a];
            mma4(S[n8], qh[k16][0], qh[k16][1], qh[k16][2], qh[k16][3], bh.x, bh.y);
            mma4(S[n8], qh[k16][0], qh[k16][1], qh[k16][2], qh[k16][3], bl.x, bl.y);
            mma4(S[n8], ql[k16][0], ql[k16][1], ql[k16][2], ql[k16][3], bh.x, bh.y);
        }
    }

    // ---- scale + bias + mask ----
    const int base_ra = (raC / 7 + 6) * 13 + raC % 7 + 6;
    const int base_rb = (rbC / 7 + 6) * 13 + rbC % 7 + 6;
#pragma unroll
    for (int n8 = 0; n8 < 7; n8++) {
#pragma unroll
        for (int e = 0; e < 2; e++) {
            const int col = n8 * 8 + qc + e;
            if (col >= NKEY) {
                S[n8][e] = -1e30f; S[n8][2 + e] = -1e30f;
            } else if (col >= NMEM) {
                const int t = tab_s[col];
                S[n8][e]     = fmaf(S[n8][e],     scale, bias_s[base_ra - t]);
                S[n8][2 + e] = fmaf(S[n8][2 + e], scale, bias_s[base_rb - t]);
            } else {
                S[n8][e] *= scale; S[n8][2 + e] *= scale;
            }
        }
    }

    // ---- softmax (rows ra, rb), fp32 exact ----
    float mA = -1e30f, mB = -1e30f;
#pragma unroll
    for (int n8 = 0; n8 < 7; n8++) {
        mA = fmaxf(mA, fmaxf(S[n8][0], S[n8][1]));
        mB = fmaxf(mB, fmaxf(S[n8][2], S[n8][3]));
    }
    mA = fmaxf(mA, __shfl_xor_sync(0xffffffffu, mA, 1));
    mA = fmaxf(mA, __shfl_xor_sync(0xffffffffu, mA, 2));
    mB = fmaxf(mB, __shfl_xor_sync(0xffffffffu, mB, 1));
    mB = fmaxf(mB, __shfl_xor_sync(0xffffffffu, mB, 2));
    float lA = 0.f, lB = 0.f;
#pragma unroll
    for (int n8 = 0; n8 < 7; n8++) {
        S[n8][0] = __expf(S[n8][0] - mA); lA += S[n8][0];
        S[n8][1] = __expf(S[n8][1] - mA); lA += S[n8][1];
        S[n8][2] = __expf(S[n8][2] - mB); lB += S[n8][2];
        S[n8][3] = __expf(S[n8][3] - mB); lB += S[n8][3];
    }
    lA += __shfl_xor_sync(0xffffffffu, lA, 1);
    lA += __shfl_xor_sync(0xffffffffu, lA, 2);
    lB += __shfl_xor_sync(0xffffffffu, lB, 1);
    lB += __shfl_xor_sync(0xffffffffu, lB, 2);
    const float invA = 1.f / lA, invB = 1.f / lB;
#pragma unroll
    for (int n8 = 0; n8 < 7; n8++) {
        S[n8][0] *= invA; S[n8][1] *= invA;
        S[n8][2] *= invB; S[n8][3] *= invB;
    }

    // ---- pack P into A-frags (hi/lo) ----
    uint32_t ph[4][4], pl[4][4];
#pragma unroll
    for (int k16 = 0; k16 < 4; k16++) {
        const int na = 2 * k16, nb = na + 1;
        split2(S[na][0], S[na][1], ph[k16][0], pl[k16][0]);
        split2(S[na][2], S[na][3], ph[k16][1], pl[k16][1]);
        if (nb < 7) {
            split2(S[nb][0], S[nb][1], ph[k16][2], pl[k16][2]);
            split2(S[nb][2], S[nb][3], ph[k16][3], pl[k16][3]);
        } else {
            ph[k16][2] = ph[k16][3] = 0; pl[k16][2] = pl[k16][3] = 0;
        }
    }

    // ---- O = P V ----
    float O[4][4];
#pragma unroll
    for (int nv = 0; nv < 4; nv++)
#pragma unroll
        for (int r = 0; r < 4; r++) O[nv][r] = 0.f;
#pragma unroll
    for (int k16 = 0; k16 < 4; k16++) {
#pragma unroll
        for (int nv = 0; nv < 4; nv++) {
            const int a = (k16 * 32 + nv * 8 + kn) * 8 + q2w;
            const uint2 vh = *(const uint2*)&VtH[a];
            const uint2 vl = *(const uint2*)&VtL[a];
            mma4(O[nv], ph[k16][0], ph[k16][1], ph[k16][2], ph[k16][3], vh.x, vh.y);
            mma4(O[nv], ph[k16][0], ph[k16][1], ph[k16][2], ph[k16][3], vl.x, vl.y);
            mma4(O[nv], pl[k16][0], pl[k16][1], pl[k16][2], pl[k16][3], vh.x, vh.y);
        }
    }

    // ---- epilogue: direct A-frag word stores for out GEMM ----
#pragma unroll
    for (int half = 0; half < 2; half++) {
        const int row = half ? rb : ra;
        if (row < WQ) {
            const size_t tok = tok0 + row;
            const size_t m16g = tok >> 4;
            const int rr = (int)(tok & 15);
            const int comp_base = (rr < 8) ? 0 : 1;
            const int lane_t = 4 * (rr & 7) + (lane & 3);
#pragma unroll
            for (int nv = 0; nv < 4; nv++) {
                const int col = nv * 8 + qc;
                const int c16 = nv >> 1;
                const size_t fragid = m16g * 16 + 2 * h + c16;
                const int comp = comp_base + ((col & 8) ? 2 : 0);
                uint32_t hw, lw;
                split2(O[nv][half * 2], O[nv][half * 2 + 1], hw, lw);
                ((uint32_t*)(g_fah + fragid * 32 + lane_t))[comp] = hw;
                ((uint32_t*)(g_fal + fragid * 32 + lane_t))[comp] = lw;
            }
        }
    }
}

// ============================================================
extern "C" void kernel_launch(void* const* d_in, const int* in_sizes, int n_in,
                              void* d_out, int out_size) {
    const float* x          = (const float*)d_in[0];
    const float* gamma      = (const float*)d_in[1];
    const float* w_qkv      = (const float*)d_in[2];
    const float* mem_kv     = (const float*)d_in[3];
    const float* bias_table = (const float*)d_in[4];
    const float* w_out      = (const float*)d_in[5];
    float* out = (float*)d_out;

    uint4 *fah, *fal;
    cudaGetSymbolAddress((void**)&fah, g_fah);
    cudaGetSymbolAddress((void**)&fal, g_fal);
    uint2 *fbh1, *fbl1, *fbh2, *fbl2;
    cudaGetSymbolAddress((void**)&fbh1, g_fbh1);
    cudaGetSymbolAddress((void**)&fbl1, g_fbl1);
    cudaGetSymbolAddress((void**)&fbh2, g_fbh2);
    cudaGetSymbolAddress((void**)&fbl2, g_fbl2);

    mem_split<<<1, 1024>>>(mem_kv);
    pack_b<<<(NQKV / 8) * 16 * 32 / 256, 256>>>(w_qkv, fbh1, fbl1, NQKV);
    pack_b<<<(DIM / 8) * 16 * 32 / 256, 256>>>(w_out, fbh2, fbl2, DIM);
    ln_pack_a<<<TOKENS / 32, 256>>>(x, gamma);
    gemm_mma<1><<<dim3(NQKV / 128, TOKENS / 128), 128>>>(fah, fal, fbh1, fbl1, nullptr, NQKV);
    attn_kernel<<<NWIN * NHEADS, 128>>>(bias_table);
    gemm_mma<0><<<dim3(DIM / 128, TOKENS / 128), 128>>>(fah, fal, fbh2, fbl2, out, DIM);
}